// round 2
// baseline (speedup 1.0000x reference)
#include <cuda_runtime.h>
#include <cstdint>

// ---------------- problem constants ----------------
#define BATCH 64
#define TSTEPS 500
#define INDIM 700
#define HID 512
#define OUTDIM 20

#define OUT_OFF 0
#define SPK_OFF 640000
#define MEM_OFF 17024000
#define TH_OFF  33408000

// ALIF constants (match float(np.exp(...)) of the reference)
#define ALPHA_C   0.9512294245007140f
#define OMALPHA_C 0.0487705754992860f
#define RO_C      0.9983347214509673f
#define OMRO_C    0.0016652785490327f

// ---------------- static device scratch ----------------
__device__ float    g_X1[(size_t)BATCH * TSTEPS * HID];     // 65.5 MB: x@Wi1^T + bi1 + bh1, [b*T+t][j]
__device__ float    g_WT[5][HID * HID];                      // transposed weights WT[h*512+j] = W[j*512+h]
__device__ unsigned g_mask[3][TSTEPS + 1][BATCH][16];        // spike bitmasks per layer per step-slot
__device__ unsigned g_ready[3][2][512];                      // arrival counters [layer][b-half][slot]

// ---------------- init: flags + transposes ----------------
__global__ void init_kernel(const float* __restrict__ Wh1, const float* __restrict__ Wi2,
                            const float* __restrict__ Wh2, const float* __restrict__ Wi3,
                            const float* __restrict__ Wh3)
{
    int idx = blockIdx.x * blockDim.x + threadIdx.x;

    if (idx < 3 * 2 * 512) {
        ((unsigned*)g_ready)[idx] = ((idx & 511) == 0) ? 16u : 0u;
    }
    if (idx < 3 * BATCH * 16) {
        int L = idx / (BATCH * 16);
        int rem = idx % (BATCH * 16);
        g_mask[L][0][rem / 16][rem % 16] = 0u;
    }
    // transpose the 5 recurrent/feedforward HxH weights
    for (int i = idx; i < HID * HID; i += gridDim.x * blockDim.x) {
        int h = i >> 9, j = i & 511;
        int src = j * HID + h;
        g_WT[0][i] = Wh1[src];
        g_WT[1][i] = Wi2[src];
        g_WT[2][i] = Wh2[src];
        g_WT[3][i] = Wi3[src];
        g_WT[4][i] = Wh3[src];
    }
}

// ---------------- X1 = x @ Wi1^T + bi1 + bh1 (fp32 SGEMM 128x128x16) ----------------
__global__ __launch_bounds__(256) void x1_gemm(const float* __restrict__ x,
                                               const float* __restrict__ Wi1,
                                               const float* __restrict__ bi1,
                                               const float* __restrict__ bh1)
{
    __shared__ float As[16][128];
    __shared__ float Bs[16][128];

    const int mBase = blockIdx.y * 128;
    const int nBase = blockIdx.x * 128;
    const int tid = threadIdx.x;
    const int tr = (tid / 16) * 8;
    const int tc = (tid % 16) * 8;

    float acc[8][8];
#pragma unroll
    for (int i = 0; i < 8; ++i)
#pragma unroll
        for (int jj = 0; jj < 8; ++jj) acc[i][jj] = 0.f;

    for (int k0 = 0; k0 < INDIM; k0 += 16) {
        // load A tile (128 rows x 16 k) transposed into As[k][m]
#pragma unroll
        for (int i = 0; i < 2; ++i) {
            int cid = tid + i * 256;
            int row = cid >> 2;
            int kq = (cid & 3) * 4;
            int k = k0 + kq;
            float4 v = make_float4(0.f, 0.f, 0.f, 0.f);
            const float* src = &x[(size_t)(mBase + row) * INDIM + k];
            if (k + 3 < INDIM) {
                v = *(const float4*)src;
            } else {
                float t0 = (k + 0 < INDIM) ? src[0] : 0.f;
                float t1 = (k + 1 < INDIM) ? src[1] : 0.f;
                float t2 = (k + 2 < INDIM) ? src[2] : 0.f;
                float t3 = (k + 3 < INDIM) ? src[3] : 0.f;
                v = make_float4(t0, t1, t2, t3);
            }
            As[kq + 0][row] = v.x; As[kq + 1][row] = v.y;
            As[kq + 2][row] = v.z; As[kq + 3][row] = v.w;
        }
        // load B tile (Wi1: 128 j rows x 16 k) into Bs[k][j]
#pragma unroll
        for (int i = 0; i < 2; ++i) {
            int cid = tid + i * 256;
            int row = cid >> 2;
            int kq = (cid & 3) * 4;
            int k = k0 + kq;
            float4 v = make_float4(0.f, 0.f, 0.f, 0.f);
            const float* src = &Wi1[(size_t)(nBase + row) * INDIM + k];
            if (k + 3 < INDIM) {
                v = *(const float4*)src;
            } else {
                float t0 = (k + 0 < INDIM) ? src[0] : 0.f;
                float t1 = (k + 1 < INDIM) ? src[1] : 0.f;
                float t2 = (k + 2 < INDIM) ? src[2] : 0.f;
                float t3 = (k + 3 < INDIM) ? src[3] : 0.f;
                v = make_float4(t0, t1, t2, t3);
            }
            Bs[kq + 0][row] = v.x; Bs[kq + 1][row] = v.y;
            Bs[kq + 2][row] = v.z; Bs[kq + 3][row] = v.w;
        }
        __syncthreads();

#pragma unroll
        for (int kk = 0; kk < 16; ++kk) {
            float a[8], b[8];
            *(float4*)&a[0] = *(float4*)&As[kk][tr];
            *(float4*)&a[4] = *(float4*)&As[kk][tr + 4];
            *(float4*)&b[0] = *(float4*)&Bs[kk][tc];
            *(float4*)&b[4] = *(float4*)&Bs[kk][tc + 4];
#pragma unroll
            for (int i = 0; i < 8; ++i)
#pragma unroll
                for (int jj = 0; jj < 8; ++jj) acc[i][jj] += a[i] * b[jj];
        }
        __syncthreads();
    }

    float bj[8];
#pragma unroll
    for (int jj = 0; jj < 8; ++jj) {
        int j = nBase + tc + jj;
        bj[jj] = bi1[j] + bh1[j];
    }
#pragma unroll
    for (int i = 0; i < 8; ++i) {
        size_t m = (size_t)(mBase + tr + i);
        float4 v0 = make_float4(acc[i][0] + bj[0], acc[i][1] + bj[1],
                                acc[i][2] + bj[2], acc[i][3] + bj[3]);
        float4 v1 = make_float4(acc[i][4] + bj[4], acc[i][5] + bj[5],
                                acc[i][6] + bj[6], acc[i][7] + bj[7]);
        *(float4*)&g_X1[m * HID + nBase + tc] = v0;
        *(float4*)&g_X1[m * HID + nBase + tc + 4] = v1;
    }
}

// ---------------- persistent pipelined ALIF loop ----------------
__device__ __forceinline__ void waitflag(const unsigned* p, unsigned target)
{
    unsigned v;
    do {
        asm volatile("ld.acquire.gpu.u32 %0, [%1];" : "=r"(v) : "l"(p) : "memory");
    } while (v < target);
}

__device__ __forceinline__ float sparse_dot(const unsigned* __restrict__ maskrow,
                                            const float* __restrict__ WT, int j)
{
    float acc = 0.f;
#pragma unroll
    for (int wd = 0; wd < 16; ++wd) {
        unsigned bits = maskrow[wd];
        const float* p = WT + (size_t)wd * 32 * HID + j;
        while (bits) {
            int k = __ffs(bits) - 1;
            bits &= bits - 1;
            acc += __ldg(&p[(size_t)k * HID]);
        }
    }
    return acc;
}

__global__ __launch_bounds__(512) void alif_persistent(const float* __restrict__ bi2,
                                                       const float* __restrict__ bh2,
                                                       const float* __restrict__ bi3,
                                                       const float* __restrict__ bh3,
                                                       float* __restrict__ out)
{
    const int cta = blockIdx.x;        // 0..95
    const int L = cta / 32;            // layer 0,1,2
    const int r = cta % 32;
    const int jt = r % 16;             // j-tile of 32
    const int bh = r / 16;             // b-half of 32
    const int tid = threadIdx.x;
    const int w = tid / 32;            // warp 0..15
    const int lane = tid % 32;
    const int j = jt * 32 + lane;
    const int b0 = bh * 32 + w * 2;
    const int b1 = b0 + 1;

    const float* WT_in = nullptr;
    const float* WT_rec = nullptr;
    float biasj = 0.f;
    if (L == 0) {
        WT_rec = g_WT[0];
    } else if (L == 1) {
        WT_in = g_WT[1]; WT_rec = g_WT[2];
        biasj = bi2[j] + bh2[j];
    } else {
        WT_in = g_WT[3]; WT_rec = g_WT[4];
        biasj = bi3[j] + bh3[j];
    }

    float m0 = 0.f, m1 = 0.f;
    float bb0 = 0.01f, bb1 = 0.01f;
    float sp0 = 0.f, sp1 = 0.f;

    for (int t = 0; t < TSTEPS; ++t) {
        if (tid == 0) {
            if (L == 0) {
                waitflag(&g_ready[0][bh][t], 16u);
            } else if (L == 1) {
                waitflag(&g_ready[0][bh][t + 1], 16u);
                waitflag(&g_ready[1][bh][t], 16u);
            } else {
                waitflag(&g_ready[1][bh][t + 1], 16u);
                waitflag(&g_ready[2][bh][t], 16u);
            }
        }
        __syncthreads();

        float a0, a1;
        if (L == 0) {
            a0 = g_X1[(size_t)(b0 * TSTEPS + t) * HID + j];
            a1 = g_X1[(size_t)(b1 * TSTEPS + t) * HID + j];
            a0 += sparse_dot(&g_mask[0][t][b0][0], WT_rec, j);
            a1 += sparse_dot(&g_mask[0][t][b1][0], WT_rec, j);
        } else if (L == 1) {
            a0 = biasj; a1 = biasj;
            a0 += sparse_dot(&g_mask[0][t + 1][b0][0], WT_in, j);
            a1 += sparse_dot(&g_mask[0][t + 1][b1][0], WT_in, j);
            a0 += sparse_dot(&g_mask[1][t][b0][0], WT_rec, j);
            a1 += sparse_dot(&g_mask[1][t][b1][0], WT_rec, j);
        } else {
            a0 = biasj; a1 = biasj;
            a0 += sparse_dot(&g_mask[1][t + 1][b0][0], WT_in, j);
            a1 += sparse_dot(&g_mask[1][t + 1][b1][0], WT_in, j);
            a0 += sparse_dot(&g_mask[2][t][b0][0], WT_rec, j);
            a1 += sparse_dot(&g_mask[2][t][b1][0], WT_rec, j);
        }

        // ALIF update (matches reference order)
        bb0 = RO_C * bb0 + OMRO_C * sp0;
        bb1 = RO_C * bb1 + OMRO_C * sp1;
        float th0 = 0.01f + 1.8f * bb0;
        float th1 = 0.01f + 1.8f * bb1;
        m0 = m0 * ALPHA_C + OMALPHA_C * a0 - th0 * sp0;
        m1 = m1 * ALPHA_C + OMALPHA_C * a1 - th1 * sp1;
        float sn0 = (m0 - th0 > 0.f) ? 1.f : 0.f;
        float sn1 = (m1 - th1 > 0.f) ? 1.f : 0.f;

        unsigned word0 = __ballot_sync(0xffffffffu, sn0 > 0.5f);
        unsigned word1 = __ballot_sync(0xffffffffu, sn1 > 0.5f);
        if (lane == 0) {
            g_mask[L][t + 1][b0][jt] = word0;
            g_mask[L][t + 1][b1][jt] = word1;
        }

        if (L == 2) {
            size_t i0 = (size_t)(b0 * TSTEPS + t) * HID + j;
            size_t i1 = (size_t)(b1 * TSTEPS + t) * HID + j;
            out[SPK_OFF + i0] = sn0;  out[SPK_OFF + i1] = sn1;
            out[MEM_OFF + i0] = m0;   out[MEM_OFF + i1] = m1;
            out[TH_OFF + i0]  = th0;  out[TH_OFF + i1]  = th1;
        }
        sp0 = sn0; sp1 = sn1;

        __threadfence();
        __syncthreads();
        if (tid == 0) atomicAdd(&g_ready[L][bh][t + 1], 1u);
    }
}

// ---------------- output = mem3 @ Wo^T + bo ----------------
__global__ __launch_bounds__(256) void out_gemm(const float* __restrict__ Wo,
                                                const float* __restrict__ bo,
                                                float* __restrict__ out)
{
    const float* mem = out + MEM_OFF;
    int warp = threadIdx.x / 32, lane = threadIdx.x % 32;
    int row = blockIdx.x * 8 + warp;   // 0..31999

    float mreg[16];
#pragma unroll
    for (int kk = 0; kk < 16; ++kk)
        mreg[kk] = mem[(size_t)row * HID + kk * 32 + lane];

#pragma unroll 4
    for (int o = 0; o < OUTDIM; ++o) {
        float s = 0.f;
#pragma unroll
        for (int kk = 0; kk < 16; ++kk)
            s += mreg[kk] * __ldg(&Wo[(size_t)o * HID + kk * 32 + lane]);
#pragma unroll
        for (int off = 16; off; off >>= 1)
            s += __shfl_xor_sync(0xffffffffu, s, off);
        if (lane == 0)
            out[OUT_OFF + (size_t)row * OUTDIM + o] = s + __ldg(&bo[o]);
    }
}

// ---------------- launch ----------------
extern "C" void kernel_launch(void* const* d_in, const int* in_sizes, int n_in,
                              void* d_out, int out_size)
{
    const float* x   = (const float*)d_in[0];
    const float* Wi1 = (const float*)d_in[1];
    const float* bi1 = (const float*)d_in[2];
    const float* Wh1 = (const float*)d_in[3];
    const float* bh1 = (const float*)d_in[4];
    const float* Wi2 = (const float*)d_in[5];
    const float* bi2 = (const float*)d_in[6];
    const float* Wh2 = (const float*)d_in[7];
    const float* bh2 = (const float*)d_in[8];
    const float* Wi3 = (const float*)d_in[9];
    const float* bi3 = (const float*)d_in[10];
    const float* Wh3 = (const float*)d_in[11];
    const float* bh3 = (const float*)d_in[12];
    const float* Wo  = (const float*)d_in[13];
    const float* bo  = (const float*)d_in[14];
    float* out = (float*)d_out;

    init_kernel<<<1024, 256>>>(Wh1, Wi2, Wh2, Wi3, Wh3);
    x1_gemm<<<dim3(HID / 128, (BATCH * TSTEPS) / 128), 256>>>(x, Wi1, bi1, bh1);
    alif_persistent<<<96, 512>>>(bi2, bh2, bi3, bh3, out);
    out_gemm<<<(BATCH * TSTEPS) / 8, 256>>>(Wo, bo, out);
}

// round 3
// speedup vs baseline: 1.7085x; 1.7085x over previous
#include <cuda_runtime.h>
#include <cstdint>

// ---------------- problem constants ----------------
#define BATCH 64
#define TSTEPS 500
#define INDIM 700
#define HID 512
#define OUTDIM 20

#define OUT_OFF 0
#define SPK_OFF 640000
#define MEM_OFF 17024000
#define TH_OFF  33408000

#define ALPHA_C   0.9512294245007140f
#define OMALPHA_C 0.0487705754992860f
#define RO_C      0.9983347214509673f
#define OMRO_C    0.0016652785490327f

// ---------------- static device scratch ----------------
__device__ float    g_X1[(size_t)BATCH * TSTEPS * HID];     // x@Wi1^T + bi1 + bh1, [b*T+t][j]
__device__ unsigned g_mask[3][TSTEPS + 1][BATCH][16];       // spike bitmasks
__device__ unsigned g_r0[TSTEPS + 1];                       // layer0 group flags
__device__ unsigned g_r1[2][TSTEPS + 1];                    // layer1 per-half flags
__device__ unsigned g_r2[2][TSTEPS + 1];                    // layer2 per-half flags

// ---------------- init: flags + t=0 masks ----------------
__global__ void init_kernel()
{
    int idx = blockIdx.x * blockDim.x + threadIdx.x;
    int n = gridDim.x * blockDim.x;
    for (int i = idx; i < TSTEPS + 1; i += n)
        g_r0[i] = (i == 0) ? 16u : 0u;
    for (int i = idx; i < 2 * (TSTEPS + 1); i += n)
        ((unsigned*)g_r1)[i] = ((i % (TSTEPS + 1)) == 0) ? 16u : 0u;
    for (int i = idx; i < 2 * (TSTEPS + 1); i += n)
        ((unsigned*)g_r2)[i] = ((i % (TSTEPS + 1)) == 0) ? 16u : 0u;
    for (int i = idx; i < 3 * BATCH * 16; i += n) {
        int L = i / (BATCH * 16);
        int r = i % (BATCH * 16);
        g_mask[L][0][r / 16][r % 16] = 0u;
    }
}

// ---------------- X1 = x @ Wi1^T + bi1 + bh1 (fp32 SGEMM 128x128x16) ----------------
__global__ __launch_bounds__(256) void x1_gemm(const float* __restrict__ x,
                                               const float* __restrict__ Wi1,
                                               const float* __restrict__ bi1,
                                               const float* __restrict__ bh1)
{
    __shared__ float As[16][128];
    __shared__ float Bs[16][128];

    const int mBase = blockIdx.y * 128;
    const int nBase = blockIdx.x * 128;
    const int tid = threadIdx.x;
    const int tr = (tid / 16) * 8;
    const int tc = (tid % 16) * 8;

    float acc[8][8];
#pragma unroll
    for (int i = 0; i < 8; ++i)
#pragma unroll
        for (int jj = 0; jj < 8; ++jj) acc[i][jj] = 0.f;

    for (int k0 = 0; k0 < INDIM; k0 += 16) {
#pragma unroll
        for (int i = 0; i < 2; ++i) {
            int cid = tid + i * 256;
            int row = cid >> 2;
            int kq = (cid & 3) * 4;
            int k = k0 + kq;
            float4 v = make_float4(0.f, 0.f, 0.f, 0.f);
            const float* src = &x[(size_t)(mBase + row) * INDIM + k];
            if (k + 3 < INDIM) {
                v = *(const float4*)src;
            } else {
                float t0 = (k + 0 < INDIM) ? src[0] : 0.f;
                float t1 = (k + 1 < INDIM) ? src[1] : 0.f;
                float t2 = (k + 2 < INDIM) ? src[2] : 0.f;
                float t3 = (k + 3 < INDIM) ? src[3] : 0.f;
                v = make_float4(t0, t1, t2, t3);
            }
            As[kq + 0][row] = v.x; As[kq + 1][row] = v.y;
            As[kq + 2][row] = v.z; As[kq + 3][row] = v.w;
        }
#pragma unroll
        for (int i = 0; i < 2; ++i) {
            int cid = tid + i * 256;
            int row = cid >> 2;
            int kq = (cid & 3) * 4;
            int k = k0 + kq;
            float4 v = make_float4(0.f, 0.f, 0.f, 0.f);
            const float* src = &Wi1[(size_t)(nBase + row) * INDIM + k];
            if (k + 3 < INDIM) {
                v = *(const float4*)src;
            } else {
                float t0 = (k + 0 < INDIM) ? src[0] : 0.f;
                float t1 = (k + 1 < INDIM) ? src[1] : 0.f;
                float t2 = (k + 2 < INDIM) ? src[2] : 0.f;
                float t3 = (k + 3 < INDIM) ? src[3] : 0.f;
                v = make_float4(t0, t1, t2, t3);
            }
            Bs[kq + 0][row] = v.x; Bs[kq + 1][row] = v.y;
            Bs[kq + 2][row] = v.z; Bs[kq + 3][row] = v.w;
        }
        __syncthreads();

#pragma unroll
        for (int kk = 0; kk < 16; ++kk) {
            float a[8], b[8];
            *(float4*)&a[0] = *(float4*)&As[kk][tr];
            *(float4*)&a[4] = *(float4*)&As[kk][tr + 4];
            *(float4*)&b[0] = *(float4*)&Bs[kk][tc];
            *(float4*)&b[4] = *(float4*)&Bs[kk][tc + 4];
#pragma unroll
            for (int i = 0; i < 8; ++i)
#pragma unroll
                for (int jj = 0; jj < 8; ++jj) acc[i][jj] += a[i] * b[jj];
        }
        __syncthreads();
    }

    float bj[8];
#pragma unroll
    for (int jj = 0; jj < 8; ++jj) {
        int j = nBase + tc + jj;
        bj[jj] = bi1[j] + bh1[j];
    }
#pragma unroll
    for (int i = 0; i < 8; ++i) {
        size_t m = (size_t)(mBase + tr + i);
        float4 v0 = make_float4(acc[i][0] + bj[0], acc[i][1] + bj[1],
                                acc[i][2] + bj[2], acc[i][3] + bj[3]);
        float4 v1 = make_float4(acc[i][4] + bj[4], acc[i][5] + bj[5],
                                acc[i][6] + bj[6], acc[i][7] + bj[7]);
        *(float4*)&g_X1[m * HID + nBase + tc] = v0;
        *(float4*)&g_X1[m * HID + nBase + tc + 4] = v1;
    }
}

// ---------------- sync helpers ----------------
__device__ __forceinline__ void waitflag(const unsigned* p, unsigned target)
{
    unsigned v;
    do {
        asm volatile("ld.acquire.gpu.u32 %0, [%1];" : "=r"(v) : "l"(p) : "memory");
    } while (v < target);
}

__device__ __forceinline__ void release_add(unsigned* p)
{
    asm volatile("red.release.gpu.add.u32 [%0], 1;" :: "l"(p) : "memory");
}

// ---------------- ALIF vector update ----------------
__device__ __forceinline__ void alif4(float4& m, float4& bb, float4& sp,
                                      const float4 a, float4& th, float4& s)
{
    bb.x = RO_C * bb.x + OMRO_C * sp.x;
    bb.y = RO_C * bb.y + OMRO_C * sp.y;
    bb.z = RO_C * bb.z + OMRO_C * sp.z;
    bb.w = RO_C * bb.w + OMRO_C * sp.w;
    th.x = 0.01f + 1.8f * bb.x;
    th.y = 0.01f + 1.8f * bb.y;
    th.z = 0.01f + 1.8f * bb.z;
    th.w = 0.01f + 1.8f * bb.w;
    m.x = m.x * ALPHA_C + OMALPHA_C * a.x - th.x * sp.x;
    m.y = m.y * ALPHA_C + OMALPHA_C * a.y - th.y * sp.y;
    m.z = m.z * ALPHA_C + OMALPHA_C * a.z - th.z * sp.z;
    m.w = m.w * ALPHA_C + OMALPHA_C * a.w - th.w * sp.w;
    s.x = (m.x - th.x > 0.f) ? 1.f : 0.f;
    s.y = (m.y - th.y > 0.f) ? 1.f : 0.f;
    s.z = (m.z - th.z > 0.f) ? 1.f : 0.f;
    s.w = (m.w - th.w > 0.f) ? 1.f : 0.f;
}

// smem layout (dynamic): Wa 64KB | Wb 64KB | stg 8KB | red 4KB | nib 2KB
#define SMEM_BYTES (65536 + 65536 + 8192 + 4096 + 2048)

// ---------------- persistent pipelined ALIF loop ----------------
__global__ __launch_bounds__(512, 1) void alif_persistent(
    const float* __restrict__ Wh1,
    const float* __restrict__ Wi2, const float* __restrict__ bi2,
    const float* __restrict__ Wh2, const float* __restrict__ bh2,
    const float* __restrict__ Wi3, const float* __restrict__ bi3,
    const float* __restrict__ Wh3, const float* __restrict__ bh3,
    float* __restrict__ out)
{
    extern __shared__ unsigned char smraw[];
    float*    Wa  = (float*)smraw;                               // [512][32]
    float*    Wb  = (float*)(smraw + 65536);                     // [512][32]
    unsigned* stg = (unsigned*)(smraw + 131072);                 // [2][64][16] (L0: [64][16])
    float*    red = (float*)(smraw + 131072 + 8192);             // [256][4]
    unsigned* nib = (unsigned*)(smraw + 131072 + 8192 + 4096);   // [64][8]

    const int cta = blockIdx.x;
    const int tid = threadIdx.x;

    if (cta < 16) {
        // ================= layer 0: 16 CTAs, each 64b x 32j, 1 matrix =================
        const int jt = cta, j0 = jt * 32;
        const int b = tid >> 3, jg = tid & 7;
        const int j = j0 + jg * 4;

        for (int idx = tid; idx < 512 * 32; idx += 512) {
            int jj = idx >> 9, h = idx & 511;
            Wa[h * 32 + jj] = Wh1[(size_t)(j0 + jj) * HID + h];
        }

        float4 m = {0, 0, 0, 0}, sp = {0, 0, 0, 0};
        float4 bb = {0.01f, 0.01f, 0.01f, 0.01f};
        const float* Wp = Wa + jg * 4;

        for (int t = 0; t < TSTEPS; ++t) {
            float4 x4 = *(const float4*)&g_X1[(size_t)(b * TSTEPS + t) * HID + j];
            if (tid == 0) waitflag(&g_r0[t], 16u);
            __syncthreads();
            if (tid < 256)
                ((uint4*)stg)[tid] = ((const uint4*)&g_mask[0][t][0][0])[tid];
            __syncthreads();

            float4 acc = {0, 0, 0, 0};
#pragma unroll
            for (int wd = 0; wd < 16; ++wd) {
                unsigned bits = stg[b * 16 + wd];
                const float* base = Wp + wd * 1024;
                while (bits) {
                    int k = __ffs(bits) - 1; bits &= bits - 1;
                    float4 w = *(const float4*)(base + k * 32);
                    acc.x += w.x; acc.y += w.y; acc.z += w.z; acc.w += w.w;
                }
            }
            float4 a = {x4.x + acc.x, x4.y + acc.y, x4.z + acc.z, x4.w + acc.w};
            float4 th, s;
            alif4(m, bb, sp, a, th, s);
            unsigned nb = (s.x != 0.f ? 1u : 0u) | (s.y != 0.f ? 2u : 0u) |
                          (s.z != 0.f ? 4u : 0u) | (s.w != 0.f ? 8u : 0u);
            nib[b * 8 + jg] = nb;
            sp = s;
            __syncthreads();
            if (tid < 64) {
                uint4 n0 = *(const uint4*)&nib[tid * 8];
                uint4 n1 = *(const uint4*)&nib[tid * 8 + 4];
                unsigned wo = n0.x | (n0.y << 4) | (n0.z << 8) | (n0.w << 12) |
                              (n1.x << 16) | (n1.y << 20) | (n1.z << 24) | (n1.w << 28);
                g_mask[0][t + 1][tid][jt] = wo;
            }
            __syncthreads();
            if (tid == 0) release_add(&g_r0[t + 1]);
        }
    } else {
        // ============ layers 1/2: 32 CTAs each, 32b x 32j, 2 matrices, split-K ============
        const int L = (cta < 48) ? 1 : 2;
        const int r = (cta - 16) & 31;
        const int jt = r & 15, half = r >> 4;
        const int j0 = jt * 32, b0 = half * 32;
        const int kh = tid >> 8, rem = tid & 255;
        const int bi = rem >> 3, jg = rem & 7;
        const int b = b0 + bi, j = j0 + jg * 4;

        const float* Win  = (L == 1) ? Wi2 : Wi3;
        const float* Wrec = (L == 1) ? Wh2 : Wh3;
        const float* bI   = (L == 1) ? bi2 : bi3;
        const float* bH   = (L == 1) ? bh2 : bh3;

        for (int idx = tid; idx < 512 * 32; idx += 512) {
            int jj = idx >> 9, h = idx & 511;
            Wa[h * 32 + jj] = Win[(size_t)(j0 + jj) * HID + h];
            Wb[h * 32 + jj] = Wrec[(size_t)(j0 + jj) * HID + h];
        }

        float4 bias = {bI[j] + bH[j], bI[j + 1] + bH[j + 1],
                       bI[j + 2] + bH[j + 2], bI[j + 3] + bH[j + 3]};
        float4 m = {0, 0, 0, 0}, sp = {0, 0, 0, 0};
        float4 bb = {0.01f, 0.01f, 0.01f, 0.01f};

        unsigned* stgA = stg;         // [32][16]
        unsigned* stgB = stg + 512;   // [32][16]
        const int wd0 = kh * 8;
        const float* WpA = Wa + jg * 4;
        const float* WpB = Wb + jg * 4;

        for (int t = 0; t < TSTEPS; ++t) {
            if (tid == 0) {
                if (L == 1) waitflag(&g_r0[t + 1], 16u);
                else        waitflag(&g_r1[half][t + 1], 16u);
            } else if (tid == 32) {
                if (L == 1) waitflag(&g_r1[half][t], 16u);
                else        waitflag(&g_r2[half][t], 16u);
            }
            __syncthreads();
            if (tid < 128) {
                ((uint4*)stgA)[tid] = (L == 1)
                    ? ((const uint4*)&g_mask[0][t + 1][b0][0])[tid]
                    : ((const uint4*)&g_mask[1][t + 1][b0][0])[tid];
            } else if (tid < 256) {
                ((uint4*)stgB)[tid - 128] = (L == 1)
                    ? ((const uint4*)&g_mask[1][t][b0][0])[tid - 128]
                    : ((const uint4*)&g_mask[2][t][b0][0])[tid - 128];
            }
            __syncthreads();

            float4 acc = {0, 0, 0, 0};
#pragma unroll
            for (int wq = 0; wq < 8; ++wq) {
                int wd = wd0 + wq;
                unsigned bits = stgA[bi * 16 + wd];
                const float* basep = WpA + wd * 1024;
                while (bits) {
                    int k = __ffs(bits) - 1; bits &= bits - 1;
                    float4 w = *(const float4*)(basep + k * 32);
                    acc.x += w.x; acc.y += w.y; acc.z += w.z; acc.w += w.w;
                }
                bits = stgB[bi * 16 + wd];
                basep = WpB + wd * 1024;
                while (bits) {
                    int k = __ffs(bits) - 1; bits &= bits - 1;
                    float4 w = *(const float4*)(basep + k * 32);
                    acc.x += w.x; acc.y += w.y; acc.z += w.z; acc.w += w.w;
                }
            }
            if (kh == 1) *(float4*)&red[rem * 4] = acc;
            __syncthreads();
            if (kh == 0) {
                float4 o = *(const float4*)&red[rem * 4];
                float4 a = {bias.x + acc.x + o.x, bias.y + acc.y + o.y,
                            bias.z + acc.z + o.z, bias.w + acc.w + o.w};
                float4 th, s;
                alif4(m, bb, sp, a, th, s);
                unsigned nb = (s.x != 0.f ? 1u : 0u) | (s.y != 0.f ? 2u : 0u) |
                              (s.z != 0.f ? 4u : 0u) | (s.w != 0.f ? 8u : 0u);
                nib[bi * 8 + jg] = nb;
                sp = s;
                if (L == 2) {
                    size_t basei = (size_t)(b * TSTEPS + t) * HID + j;
                    *(float4*)&out[SPK_OFF + basei] = s;
                    *(float4*)&out[MEM_OFF + basei] = m;
                    *(float4*)&out[TH_OFF + basei]  = th;
                }
            }
            __syncthreads();
            if (tid < 32) {
                uint4 n0 = *(const uint4*)&nib[tid * 8];
                uint4 n1 = *(const uint4*)&nib[tid * 8 + 4];
                unsigned wo = n0.x | (n0.y << 4) | (n0.z << 8) | (n0.w << 12) |
                              (n1.x << 16) | (n1.y << 20) | (n1.z << 24) | (n1.w << 28);
                g_mask[L][t + 1][b0 + tid][jt] = wo;
            }
            __syncthreads();
            if (tid == 0) {
                if (L == 1) release_add(&g_r1[half][t + 1]);
                else        release_add(&g_r2[half][t + 1]);
            }
        }
    }
}

// ---------------- output = mem3 @ Wo^T + bo ----------------
__global__ __launch_bounds__(256) void out_gemm(const float* __restrict__ Wo,
                                                const float* __restrict__ bo,
                                                float* __restrict__ out)
{
    const float* mem = out + MEM_OFF;
    int warp = threadIdx.x / 32, lane = threadIdx.x % 32;
    int row = blockIdx.x * 8 + warp;

    float mreg[16];
#pragma unroll
    for (int kk = 0; kk < 16; ++kk)
        mreg[kk] = mem[(size_t)row * HID + kk * 32 + lane];

#pragma unroll 4
    for (int o = 0; o < OUTDIM; ++o) {
        float s = 0.f;
#pragma unroll
        for (int kk = 0; kk < 16; ++kk)
            s += mreg[kk] * __ldg(&Wo[(size_t)o * HID + kk * 32 + lane]);
#pragma unroll
        for (int off = 16; off; off >>= 1)
            s += __shfl_xor_sync(0xffffffffu, s, off);
        if (lane == 0)
            out[OUT_OFF + (size_t)row * OUTDIM + o] = s + __ldg(&bo[o]);
    }
}

// ---------------- launch ----------------
extern "C" void kernel_launch(void* const* d_in, const int* in_sizes, int n_in,
                              void* d_out, int out_size)
{
    const float* x   = (const float*)d_in[0];
    const float* Wi1 = (const float*)d_in[1];
    const float* bi1 = (const float*)d_in[2];
    const float* Wh1 = (const float*)d_in[3];
    const float* bh1 = (const float*)d_in[4];
    const float* Wi2 = (const float*)d_in[5];
    const float* bi2 = (const float*)d_in[6];
    const float* Wh2 = (const float*)d_in[7];
    const float* bh2 = (const float*)d_in[8];
    const float* Wi3 = (const float*)d_in[9];
    const float* bi3 = (const float*)d_in[10];
    const float* Wh3 = (const float*)d_in[11];
    const float* bh3 = (const float*)d_in[12];
    const float* Wo  = (const float*)d_in[13];
    const float* bo  = (const float*)d_in[14];
    float* out = (float*)d_out;

    static int smem_set = 0;
    if (!smem_set) {
        cudaFuncSetAttribute(alif_persistent,
                             cudaFuncAttributeMaxDynamicSharedMemorySize, SMEM_BYTES);
        smem_set = 1;
    }

    init_kernel<<<16, 256>>>();
    x1_gemm<<<dim3(HID / 128, (BATCH * TSTEPS) / 128), 256>>>(x, Wi1, bi1, bh1);
    alif_persistent<<<80, 512, SMEM_BYTES>>>(Wh1, Wi2, bi2, Wh2, bh2,
                                             Wi3, bi3, Wh3, bh3, out);
    out_gemm<<<(BATCH * TSTEPS) / 8, 256>>>(Wo, bo, out);
}

// round 4
// speedup vs baseline: 2.6547x; 1.5539x over previous
#include <cuda_runtime.h>
#include <cstdint>

// ---------------- problem constants ----------------
#define BATCH 64
#define TSTEPS 500
#define INDIM 700
#define HID 512
#define OUTDIM 20

#define OUT_OFF 0
#define SPK_OFF 640000
#define MEM_OFF 17024000
#define TH_OFF  33408000

#define ALPHA_C   0.9512294245007140f
#define OMALPHA_C 0.0487705754992860f
#define RO_C      0.9983347214509673f
#define OMRO_C    0.0016652785490327f

// ---------------- static device scratch ----------------
__device__ float    g_X1[(size_t)BATCH * TSTEPS * HID];     // x@Wi1^T + bi1 + bh1, [b*T+t][j]
__device__ unsigned g_mask[3][TSTEPS + 1][BATCH][16];       // spike bitmasks
__device__ unsigned g_r0[TSTEPS + 1];                       // layer0 group flags
__device__ unsigned g_r1[2][TSTEPS + 1];                    // layer1 per-half flags
__device__ unsigned g_r2[2][TSTEPS + 1];                    // layer2 per-half flags

// ---------------- init: flags + t=0 masks ----------------
__global__ void init_kernel()
{
    int idx = blockIdx.x * blockDim.x + threadIdx.x;
    int n = gridDim.x * blockDim.x;
    for (int i = idx; i < TSTEPS + 1; i += n)
        g_r0[i] = (i == 0) ? 16u : 0u;
    for (int i = idx; i < 2 * (TSTEPS + 1); i += n)
        ((unsigned*)g_r1)[i] = ((i % (TSTEPS + 1)) == 0) ? 16u : 0u;
    for (int i = idx; i < 2 * (TSTEPS + 1); i += n)
        ((unsigned*)g_r2)[i] = ((i % (TSTEPS + 1)) == 0) ? 16u : 0u;
    for (int i = idx; i < 3 * BATCH * 16; i += n) {
        int L = i / (BATCH * 16);
        int r = i % (BATCH * 16);
        g_mask[L][0][r / 16][r % 16] = 0u;
    }
}

// ---------------- X1 = x @ Wi1^T + bi1 + bh1 (fp32 SGEMM 128x128x16) ----------------
__global__ __launch_bounds__(256) void x1_gemm(const float* __restrict__ x,
                                               const float* __restrict__ Wi1,
                                               const float* __restrict__ bi1,
                                               const float* __restrict__ bh1)
{
    __shared__ float As[16][128];
    __shared__ float Bs[16][128];

    const int mBase = blockIdx.y * 128;
    const int nBase = blockIdx.x * 128;
    const int tid = threadIdx.x;
    const int tr = (tid / 16) * 8;
    const int tc = (tid % 16) * 8;

    float acc[8][8];
#pragma unroll
    for (int i = 0; i < 8; ++i)
#pragma unroll
        for (int jj = 0; jj < 8; ++jj) acc[i][jj] = 0.f;

    for (int k0 = 0; k0 < INDIM; k0 += 16) {
#pragma unroll
        for (int i = 0; i < 2; ++i) {
            int cid = tid + i * 256;
            int row = cid >> 2;
            int kq = (cid & 3) * 4;
            int k = k0 + kq;
            float4 v = make_float4(0.f, 0.f, 0.f, 0.f);
            const float* src = &x[(size_t)(mBase + row) * INDIM + k];
            if (k + 3 < INDIM) {
                v = *(const float4*)src;
            } else {
                float t0 = (k + 0 < INDIM) ? src[0] : 0.f;
                float t1 = (k + 1 < INDIM) ? src[1] : 0.f;
                float t2 = (k + 2 < INDIM) ? src[2] : 0.f;
                float t3 = (k + 3 < INDIM) ? src[3] : 0.f;
                v = make_float4(t0, t1, t2, t3);
            }
            As[kq + 0][row] = v.x; As[kq + 1][row] = v.y;
            As[kq + 2][row] = v.z; As[kq + 3][row] = v.w;
        }
#pragma unroll
        for (int i = 0; i < 2; ++i) {
            int cid = tid + i * 256;
            int row = cid >> 2;
            int kq = (cid & 3) * 4;
            int k = k0 + kq;
            float4 v = make_float4(0.f, 0.f, 0.f, 0.f);
            const float* src = &Wi1[(size_t)(nBase + row) * INDIM + k];
            if (k + 3 < INDIM) {
                v = *(const float4*)src;
            } else {
                float t0 = (k + 0 < INDIM) ? src[0] : 0.f;
                float t1 = (k + 1 < INDIM) ? src[1] : 0.f;
                float t2 = (k + 2 < INDIM) ? src[2] : 0.f;
                float t3 = (k + 3 < INDIM) ? src[3] : 0.f;
                v = make_float4(t0, t1, t2, t3);
            }
            Bs[kq + 0][row] = v.x; Bs[kq + 1][row] = v.y;
            Bs[kq + 2][row] = v.z; Bs[kq + 3][row] = v.w;
        }
        __syncthreads();

#pragma unroll
        for (int kk = 0; kk < 16; ++kk) {
            float a[8], b[8];
            *(float4*)&a[0] = *(float4*)&As[kk][tr];
            *(float4*)&a[4] = *(float4*)&As[kk][tr + 4];
            *(float4*)&b[0] = *(float4*)&Bs[kk][tc];
            *(float4*)&b[4] = *(float4*)&Bs[kk][tc + 4];
#pragma unroll
            for (int i = 0; i < 8; ++i)
#pragma unroll
                for (int jj = 0; jj < 8; ++jj) acc[i][jj] += a[i] * b[jj];
        }
        __syncthreads();
    }

    float bj[8];
#pragma unroll
    for (int jj = 0; jj < 8; ++jj) {
        int j = nBase + tc + jj;
        bj[jj] = bi1[j] + bh1[j];
    }
#pragma unroll
    for (int i = 0; i < 8; ++i) {
        size_t m = (size_t)(mBase + tr + i);
        float4 v0 = make_float4(acc[i][0] + bj[0], acc[i][1] + bj[1],
                                acc[i][2] + bj[2], acc[i][3] + bj[3]);
        float4 v1 = make_float4(acc[i][4] + bj[4], acc[i][5] + bj[5],
                                acc[i][6] + bj[6], acc[i][7] + bj[7]);
        *(float4*)&g_X1[m * HID + nBase + tc] = v0;
        *(float4*)&g_X1[m * HID + nBase + tc + 4] = v1;
    }
}

// ---------------- sync helpers ----------------
__device__ __forceinline__ void waitflag(const unsigned* p, unsigned target)
{
    unsigned v;
    do {
        asm volatile("ld.acquire.gpu.u32 %0, [%1];" : "=r"(v) : "l"(p) : "memory");
    } while (v < target);
}

__device__ __forceinline__ void release_add(unsigned* p)
{
    asm volatile("red.release.gpu.add.u32 [%0], 1;" :: "l"(p) : "memory");
}

// ---------------- ALIF vector update ----------------
__device__ __forceinline__ void alif4(float4& m, float4& bb, float4& sp,
                                      const float4 a, float4& th, float4& s)
{
    bb.x = RO_C * bb.x + OMRO_C * sp.x;
    bb.y = RO_C * bb.y + OMRO_C * sp.y;
    bb.z = RO_C * bb.z + OMRO_C * sp.z;
    bb.w = RO_C * bb.w + OMRO_C * sp.w;
    th.x = 0.01f + 1.8f * bb.x;
    th.y = 0.01f + 1.8f * bb.y;
    th.z = 0.01f + 1.8f * bb.z;
    th.w = 0.01f + 1.8f * bb.w;
    m.x = m.x * ALPHA_C + OMALPHA_C * a.x - th.x * sp.x;
    m.y = m.y * ALPHA_C + OMALPHA_C * a.y - th.y * sp.y;
    m.z = m.z * ALPHA_C + OMALPHA_C * a.z - th.z * sp.z;
    m.w = m.w * ALPHA_C + OMALPHA_C * a.w - th.w * sp.w;
    s.x = (m.x - th.x > 0.f) ? 1.f : 0.f;
    s.y = (m.y - th.y > 0.f) ? 1.f : 0.f;
    s.z = (m.z - th.z > 0.f) ? 1.f : 0.f;
    s.w = (m.w - th.w > 0.f) ? 1.f : 0.f;
}

// smem layout (dynamic): Wa 64KB | Wb 64KB | stg 8KB | red 4KB | nib 2KB
#define SMEM_BYTES (65536 + 65536 + 8192 + 4096 + 2048)

// ---------------- persistent pipelined ALIF loop ----------------
__global__ __launch_bounds__(512, 1) void alif_persistent(
    const float* __restrict__ Wh1,
    const float* __restrict__ Wi2, const float* __restrict__ bi2,
    const float* __restrict__ Wh2, const float* __restrict__ bh2,
    const float* __restrict__ Wi3, const float* __restrict__ bi3,
    const float* __restrict__ Wh3, const float* __restrict__ bh3,
    float* __restrict__ out)
{
    extern __shared__ unsigned char smraw[];
    float*    Wa  = (float*)smraw;                               // [512][32]
    float*    Wb  = (float*)(smraw + 65536);                     // [512][32]
    unsigned* stg = (unsigned*)(smraw + 131072);                 // [2][64][16] (L0: [64][16])
    float*    red = (float*)(smraw + 131072 + 8192);             // [256][4]
    unsigned* nib = (unsigned*)(smraw + 131072 + 8192 + 4096);   // [64][8]

    const int cta = blockIdx.x;
    const int tid = threadIdx.x;

    if (cta < 16) {
        // ================= layer 0: 16 CTAs, each 64b x 32j, 1 matrix =================
        const int jt = cta, j0 = jt * 32;
        const int b = tid >> 3, jg = tid & 7;
        const int j = j0 + jg * 4;

        for (int idx = tid; idx < 512 * 32; idx += 512) {
            int jj = idx >> 9, h = idx & 511;
            Wa[h * 32 + jj] = Wh1[(size_t)(j0 + jj) * HID + h];
        }

        float4 m = {0, 0, 0, 0}, sp = {0, 0, 0, 0};
        float4 bb = {0.01f, 0.01f, 0.01f, 0.01f};
        const float* Wp = Wa + jg * 4;

        for (int t = 0; t < TSTEPS; ++t) {
            float4 x4 = *(const float4*)&g_X1[(size_t)(b * TSTEPS + t) * HID + j];
            if (tid == 0) waitflag(&g_r0[t], 16u);
            __syncthreads();
            if (tid < 256)
                ((uint4*)stg)[tid] = ((const uint4*)&g_mask[0][t][0][0])[tid];
            __syncthreads();

            float4 acc = {0, 0, 0, 0};
#pragma unroll
            for (int wd = 0; wd < 16; ++wd) {
                unsigned bits = stg[b * 16 + wd];
                const float* base = Wp + wd * 1024;
                while (bits) {
                    int k = __ffs(bits) - 1; bits &= bits - 1;
                    float4 w = *(const float4*)(base + k * 32);
                    acc.x += w.x; acc.y += w.y; acc.z += w.z; acc.w += w.w;
                }
            }
            float4 a = {x4.x + acc.x, x4.y + acc.y, x4.z + acc.z, x4.w + acc.w};
            float4 th, s;
            alif4(m, bb, sp, a, th, s);
            unsigned nb = (s.x != 0.f ? 1u : 0u) | (s.y != 0.f ? 2u : 0u) |
                          (s.z != 0.f ? 4u : 0u) | (s.w != 0.f ? 8u : 0u);
            nib[b * 8 + jg] = nb;
            sp = s;
            __syncthreads();
            if (tid < 64) {
                uint4 n0 = *(const uint4*)&nib[tid * 8];
                uint4 n1 = *(const uint4*)&nib[tid * 8 + 4];
                unsigned wo = n0.x | (n0.y << 4) | (n0.z << 8) | (n0.w << 12) |
                              (n1.x << 16) | (n1.y << 20) | (n1.z << 24) | (n1.w << 28);
                g_mask[0][t + 1][tid][jt] = wo;
            }
            __syncthreads();
            if (tid == 0) release_add(&g_r0[t + 1]);
        }
    } else {
        // ============ layers 1/2: 32 CTAs each, 32b x 32j, 2 matrices, split-K ============
        const int L = (cta < 48) ? 1 : 2;
        const int r = (cta - 16) & 31;
        const int jt = r & 15, half = r >> 4;
        const int j0 = jt * 32, b0 = half * 32;
        const int kh = tid >> 8, rem = tid & 255;
        const int bi = rem >> 3, jg = rem & 7;
        const int b = b0 + bi, j = j0 + jg * 4;

        const float* Win  = (L == 1) ? Wi2 : Wi3;
        const float* Wrec = (L == 1) ? Wh2 : Wh3;
        const float* bI   = (L == 1) ? bi2 : bi3;
        const float* bH   = (L == 1) ? bh2 : bh3;

        for (int idx = tid; idx < 512 * 32; idx += 512) {
            int jj = idx >> 9, h = idx & 511;
            Wa[h * 32 + jj] = Win[(size_t)(j0 + jj) * HID + h];
            Wb[h * 32 + jj] = Wrec[(size_t)(j0 + jj) * HID + h];
        }

        float4 bias = {bI[j] + bH[j], bI[j + 1] + bH[j + 1],
                       bI[j + 2] + bH[j + 2], bI[j + 3] + bH[j + 3]};
        float4 m = {0, 0, 0, 0}, sp = {0, 0, 0, 0};
        float4 bb = {0.01f, 0.01f, 0.01f, 0.01f};

        unsigned* stgA = stg;         // [32][16]
        unsigned* stgB = stg + 512;   // [32][16]
        const int wd0 = kh * 8;
        const float* WpA = Wa + jg * 4;
        const float* WpB = Wb + jg * 4;

        for (int t = 0; t < TSTEPS; ++t) {
            if (tid == 0) {
                if (L == 1) waitflag(&g_r0[t + 1], 16u);
                else        waitflag(&g_r1[half][t + 1], 16u);
            } else if (tid == 32) {
                if (L == 1) waitflag(&g_r1[half][t], 16u);
                else        waitflag(&g_r2[half][t], 16u);
            }
            __syncthreads();
            if (tid < 128) {
                ((uint4*)stgA)[tid] = (L == 1)
                    ? ((const uint4*)&g_mask[0][t + 1][b0][0])[tid]
                    : ((const uint4*)&g_mask[1][t + 1][b0][0])[tid];
            } else if (tid < 256) {
                ((uint4*)stgB)[tid - 128] = (L == 1)
                    ? ((const uint4*)&g_mask[1][t][b0][0])[tid - 128]
                    : ((const uint4*)&g_mask[2][t][b0][0])[tid - 128];
            }
            __syncthreads();

            float4 acc = {0, 0, 0, 0};
#pragma unroll
            for (int wq = 0; wq < 8; ++wq) {
                int wd = wd0 + wq;
                unsigned bits = stgA[bi * 16 + wd];
                const float* basep = WpA + wd * 1024;
                while (bits) {
                    int k = __ffs(bits) - 1; bits &= bits - 1;
                    float4 w = *(const float4*)(basep + k * 32);
                    acc.x += w.x; acc.y += w.y; acc.z += w.z; acc.w += w.w;
                }
                bits = stgB[bi * 16 + wd];
                basep = WpB + wd * 1024;
                while (bits) {
                    int k = __ffs(bits) - 1; bits &= bits - 1;
                    float4 w = *(const float4*)(basep + k * 32);
                    acc.x += w.x; acc.y += w.y; acc.z += w.z; acc.w += w.w;
                }
            }
            if (kh == 1) *(float4*)&red[rem * 4] = acc;
            __syncthreads();
            if (kh == 0) {
                float4 o = *(const float4*)&red[rem * 4];
                float4 a = {bias.x + acc.x + o.x, bias.y + acc.y + o.y,
                            bias.z + acc.z + o.z, bias.w + acc.w + o.w};
                float4 th, s;
                alif4(m, bb, sp, a, th, s);
                unsigned nb = (s.x != 0.f ? 1u : 0u) | (s.y != 0.f ? 2u : 0u) |
                              (s.z != 0.f ? 4u : 0u) | (s.w != 0.f ? 8u : 0u);
                nib[bi * 8 + jg] = nb;
                sp = s;
                if (L == 2) {
                    size_t basei = (size_t)(b * TSTEPS + t) * HID + j;
                    *(float4*)&out[SPK_OFF + basei] = s;
                    *(float4*)&out[MEM_OFF + basei] = m;
                    *(float4*)&out[TH_OFF + basei]  = th;
                }
            }
            __syncthreads();
            if (tid < 32) {
                uint4 n0 = *(const uint4*)&nib[tid * 8];
                uint4 n1 = *(const uint4*)&nib[tid * 8 + 4];
                unsigned wo = n0.x | (n0.y << 4) | (n0.z << 8) | (n0.w << 12) |
                              (n1.x << 16) | (n1.y << 20) | (n1.z << 24) | (n1.w << 28);
                g_mask[L][t + 1][b0 + tid][jt] = wo;
            }
            __syncthreads();
            if (tid == 0) {
                if (L == 1) release_add(&g_r1[half][t + 1]);
                else        release_add(&g_r2[half][t + 1]);
            }
        }
    }
}

// ---------------- output = mem3 @ Wo^T + bo ----------------
__global__ __launch_bounds__(256) void out_gemm(const float* __restrict__ Wo,
                                                const float* __restrict__ bo,
                                                float* __restrict__ out)
{
    const float* mem = out + MEM_OFF;
    int warp = threadIdx.x / 32, lane = threadIdx.x % 32;
    int row = blockIdx.x * 8 + warp;

    float mreg[16];
#pragma unroll
    for (int kk = 0; kk < 16; ++kk)
        mreg[kk] = mem[(size_t)row * HID + kk * 32 + lane];

#pragma unroll 4
    for (int o = 0; o < OUTDIM; ++o) {
        float s = 0.f;
#pragma unroll
        for (int kk = 0; kk < 16; ++kk)
            s += mreg[kk] * __ldg(&Wo[(size_t)o * HID + kk * 32 + lane]);
#pragma unroll
        for (int off = 16; off; off >>= 1)
            s += __shfl_xor_sync(0xffffffffu, s, off);
        if (lane == 0)
            out[OUT_OFF + (size_t)row * OUTDIM + o] = s + __ldg(&bo[o]);
    }
}

// ---------------- launch ----------------
extern "C" void kernel_launch(void* const* d_in, const int* in_sizes, int n_in,
                              void* d_out, int out_size)
{
    const float* x   = (const float*)d_in[0];
    const float* Wi1 = (const float*)d_in[1];
    const float* bi1 = (const float*)d_in[2];
    const float* Wh1 = (const float*)d_in[3];
    const float* bh1 = (const float*)d_in[4];
    const float* Wi2 = (const float*)d_in[5];
    const float* bi2 = (const float*)d_in[6];
    const float* Wh2 = (const float*)d_in[7];
    const float* bh2 = (const float*)d_in[8];
    const float* Wi3 = (const float*)d_in[9];
    const float* bi3 = (const float*)d_in[10];
    const float* Wh3 = (const float*)d_in[11];
    const float* bh3 = (const float*)d_in[12];
    const float* Wo  = (const float*)d_in[13];
    const float* bo  = (const float*)d_in[14];
    float* out = (float*)d_out;

    static int smem_set = 0;
    if (!smem_set) {
        cudaFuncSetAttribute(alif_persistent,
                             cudaFuncAttributeMaxDynamicSharedMemorySize, SMEM_BYTES);
        smem_set = 1;
    }

    init_kernel<<<16, 256>>>();
    x1_gemm<<<dim3(HID / 128, (BATCH * TSTEPS) / 128), 256>>>(x, Wi1, bi1, bh1);
    alif_persistent<<<80, 512, SMEM_BYTES>>>(Wh1, Wi2, bi2, Wh2, bh2,
                                             Wi3, bi3, Wh3, bh3, out);
    out_gemm<<<(BATCH * TSTEPS) / 8, 256>>>(Wo, bo, out);
}

// round 9
// speedup vs baseline: 3.2319x; 1.2174x over previous
#include <cuda_runtime.h>
#include <cstdint>

// ---------------- problem constants ----------------
#define BATCH 64
#define TSTEPS 500
#define INDIM 700
#define HID 512
#define OUTDIM 20

#define OUT_OFF 0
#define SPK_OFF 640000
#define MEM_OFF 17024000
#define TH_OFF  33408000

#define ALPHA_C   0.9512294245007140f
#define OMALPHA_C 0.0487705754992860f
#define RO_C      0.9983347214509673f
#define OMRO_C    0.0016652785490327f

// ---------------- static device scratch ----------------
// g_X1 layout: [t*64 + b][j]  (t-major: one GEMM y-tile = one t-pair, all batches)
__device__ float    g_X1[(size_t)BATCH * TSTEPS * HID];
__device__ unsigned g_mask[3][TSTEPS + 1][BATCH][16];    // spike bitmasks
__device__ unsigned g_r0[TSTEPS + 1];                    // layer0 group flags
__device__ unsigned g_r1[2][TSTEPS + 1];                 // layer1 per-half flags
__device__ unsigned g_r2[2][TSTEPS + 1];                 // layer2 per-half flags
__device__ unsigned g_xf[256];                           // X1 y-tile flags (target 4)

// ---------------- init: flags + t=0 masks ----------------
__global__ void init_kernel()
{
    int idx = blockIdx.x * blockDim.x + threadIdx.x;
    int n = gridDim.x * blockDim.x;
    for (int i = idx; i < TSTEPS + 1; i += n)
        g_r0[i] = (i == 0) ? 16u : 0u;
    for (int i = idx; i < 2 * (TSTEPS + 1); i += n)
        ((unsigned*)g_r1)[i] = ((i % (TSTEPS + 1)) == 0) ? 16u : 0u;
    for (int i = idx; i < 2 * (TSTEPS + 1); i += n)
        ((unsigned*)g_r2)[i] = ((i % (TSTEPS + 1)) == 0) ? 16u : 0u;
    for (int i = idx; i < 256; i += n)
        g_xf[i] = 0u;
    for (int i = idx; i < 3 * BATCH * 16; i += n) {
        int L = i / (BATCH * 16);
        int r = i % (BATCH * 16);
        g_mask[L][0][r / 16][r % 16] = 0u;
    }
}

// ---------------- sync helpers ----------------
__device__ __forceinline__ void waitflag(const unsigned* p, unsigned target)
{
    unsigned v;
    do {
        asm volatile("ld.acquire.gpu.u32 %0, [%1];" : "=r"(v) : "l"(p) : "memory");
    } while (v < target);
}

__device__ __forceinline__ void release_add(unsigned* p)
{
    asm volatile("red.release.gpu.add.u32 [%0], 1;" :: "l"(p) : "memory");
}

// ---------------- ALIF vector update ----------------
__device__ __forceinline__ void alif4(float4& m, float4& bb, float4& sp,
                                      const float4 a, float4& th, float4& s)
{
    bb.x = RO_C * bb.x + OMRO_C * sp.x;
    bb.y = RO_C * bb.y + OMRO_C * sp.y;
    bb.z = RO_C * bb.z + OMRO_C * sp.z;
    bb.w = RO_C * bb.w + OMRO_C * sp.w;
    th.x = 0.01f + 1.8f * bb.x;
    th.y = 0.01f + 1.8f * bb.y;
    th.z = 0.01f + 1.8f * bb.z;
    th.w = 0.01f + 1.8f * bb.w;
    m.x = m.x * ALPHA_C + OMALPHA_C * a.x - th.x * sp.x;
    m.y = m.y * ALPHA_C + OMALPHA_C * a.y - th.y * sp.y;
    m.z = m.z * ALPHA_C + OMALPHA_C * a.z - th.z * sp.z;
    m.w = m.w * ALPHA_C + OMALPHA_C * a.w - th.w * sp.w;
    s.x = (m.x - th.x > 0.f) ? 1.f : 0.f;
    s.y = (m.y - th.y > 0.f) ? 1.f : 0.f;
    s.z = (m.z - th.z > 0.f) ? 1.f : 0.f;
    s.w = (m.w - th.w > 0.f) ? 1.f : 0.f;
}

// smem layout (dynamic): Wa 64KB | Wb 64KB | stg 8KB | red 4KB | nib 2KB
// x1-group CTAs reuse the same region as As 8KB | Bs 8KB.
#define SMEM_BYTES (65536 + 65536 + 8192 + 4096 + 2048)

// ---------------- fused persistent kernel ----------------
// Grid = 148 CTAs x 512 thr, 1 CTA/SM (smem-bound) -> all co-resident.
//  [0,16)   L0 ALIF   (round-3 code, + X1-tile wait)
//  [16,80)  L1/L2 ALIF (round-3 code, verbatim)
//  [80,148) x1 GEMM workers (produce g_X1 tiles in t order)
__global__ __launch_bounds__(512, 1) void alif_persistent(
    const float* __restrict__ x,
    const float* __restrict__ Wi1, const float* __restrict__ bi1,
    const float* __restrict__ bh1,
    const float* __restrict__ Wh1,
    const float* __restrict__ Wi2, const float* __restrict__ bi2,
    const float* __restrict__ Wh2, const float* __restrict__ bh2,
    const float* __restrict__ Wi3, const float* __restrict__ bi3,
    const float* __restrict__ Wh3, const float* __restrict__ bh3,
    float* __restrict__ out)
{
    extern __shared__ unsigned char smraw[];
    const int cta = blockIdx.x;
    const int tid = threadIdx.x;

    if (cta >= 80) {
        // ================= x1 GEMM group: 68 CTAs over 1000 tiles =================
        float (*As)[128] = (float (*)[128])smraw;            // [16][128]
        float (*Bs)[128] = (float (*)[128])(smraw + 8192);   // [16][128]

        const int tr = (tid / 16) * 4;    // 4 rows per thread (512 threads)
        const int tc = (tid % 16) * 8;

        for (int tile = cta - 80; tile < 1000; tile += 68) {
            const int yb = tile >> 2;          // t-pair index
            const int mBase = yb * 128;
            const int nBase = (tile & 3) * 128;

            float acc[4][8];
#pragma unroll
            for (int i = 0; i < 4; ++i)
#pragma unroll
                for (int jj = 0; jj < 8; ++jj) acc[i][jj] = 0.f;

            for (int k0 = 0; k0 < INDIM; k0 += 16) {
                {
                    int row = tid >> 2;
                    int kq = (tid & 3) * 4;
                    int k = k0 + kq;
                    int R = mBase + row;
                    int tt = R >> 6, bb2 = R & 63;
                    float4 v = make_float4(0.f, 0.f, 0.f, 0.f);
                    const float* src = &x[((size_t)bb2 * TSTEPS + tt) * INDIM + k];
                    if (k + 3 < INDIM) {
                        v = *(const float4*)src;
                    } else {
                        float t0 = (k + 0 < INDIM) ? src[0] : 0.f;
                        float t1 = (k + 1 < INDIM) ? src[1] : 0.f;
                        float t2 = (k + 2 < INDIM) ? src[2] : 0.f;
                        float t3 = (k + 3 < INDIM) ? src[3] : 0.f;
                        v = make_float4(t0, t1, t2, t3);
                    }
                    As[kq + 0][row] = v.x; As[kq + 1][row] = v.y;
                    As[kq + 2][row] = v.z; As[kq + 3][row] = v.w;

                    float4 u = make_float4(0.f, 0.f, 0.f, 0.f);
                    const float* srcB = &Wi1[(size_t)(nBase + row) * INDIM + k];
                    if (k + 3 < INDIM) {
                        u = *(const float4*)srcB;
                    } else {
                        float t0 = (k + 0 < INDIM) ? srcB[0] : 0.f;
                        float t1 = (k + 1 < INDIM) ? srcB[1] : 0.f;
                        float t2 = (k + 2 < INDIM) ? srcB[2] : 0.f;
                        float t3 = (k + 3 < INDIM) ? srcB[3] : 0.f;
                        u = make_float4(t0, t1, t2, t3);
                    }
                    Bs[kq + 0][row] = u.x; Bs[kq + 1][row] = u.y;
                    Bs[kq + 2][row] = u.z; Bs[kq + 3][row] = u.w;
                }
                __syncthreads();

#pragma unroll
                for (int kk = 0; kk < 16; ++kk) {
                    float a[4], b[8];
                    *(float4*)&a[0] = *(float4*)&As[kk][tr];
                    *(float4*)&b[0] = *(float4*)&Bs[kk][tc];
                    *(float4*)&b[4] = *(float4*)&Bs[kk][tc + 4];
#pragma unroll
                    for (int i = 0; i < 4; ++i)
#pragma unroll
                        for (int jj = 0; jj < 8; ++jj) acc[i][jj] += a[i] * b[jj];
                }
                __syncthreads();
            }

            float bj[8];
#pragma unroll
            for (int jj = 0; jj < 8; ++jj) {
                int j = nBase + tc + jj;
                bj[jj] = bi1[j] + bh1[j];
            }
#pragma unroll
            for (int i = 0; i < 4; ++i) {
                size_t m = (size_t)(mBase + tr + i);
                float4 v0 = make_float4(acc[i][0] + bj[0], acc[i][1] + bj[1],
                                        acc[i][2] + bj[2], acc[i][3] + bj[3]);
                float4 v1 = make_float4(acc[i][4] + bj[4], acc[i][5] + bj[5],
                                        acc[i][6] + bj[6], acc[i][7] + bj[7]);
                *(float4*)&g_X1[m * HID + nBase + tc] = v0;
                *(float4*)&g_X1[m * HID + nBase + tc + 4] = v1;
            }
            __syncthreads();
            if (tid == 0) release_add(&g_xf[yb]);
        }
        return;
    }

    float*    Wa  = (float*)smraw;                               // [512][32]
    float*    Wb  = (float*)(smraw + 65536);                     // [512][32]
    unsigned* stg = (unsigned*)(smraw + 131072);                 // [2][64][16] (L0: [64][16])
    float*    red = (float*)(smraw + 131072 + 8192);             // [256][4]
    unsigned* nib = (unsigned*)(smraw + 131072 + 8192 + 4096);   // [64][8]

    if (cta < 16) {
        // ================= layer 0: 16 CTAs, each 64b x 32j, 1 matrix =================
        const int jt = cta, j0 = jt * 32;
        const int b = tid >> 3, jg = tid & 7;
        const int j = j0 + jg * 4;

        for (int idx = tid; idx < 512 * 32; idx += 512) {
            int jj = idx >> 9, h = idx & 511;
            Wa[h * 32 + jj] = Wh1[(size_t)(j0 + jj) * HID + h];
        }

        float4 m = {0, 0, 0, 0}, sp = {0, 0, 0, 0};
        float4 bb = {0.01f, 0.01f, 0.01f, 0.01f};
        const float* Wp = Wa + jg * 4;

        for (int t = 0; t < TSTEPS; ++t) {
            if (tid == 0) {
                waitflag(&g_xf[t >> 1], 4u);   // X1 tile for this t-pair ready
                waitflag(&g_r0[t], 16u);
            }
            __syncthreads();
            float4 x4 = *(const float4*)&g_X1[((size_t)t * 64 + b) * HID + j];
            if (tid < 256)
                ((uint4*)stg)[tid] = ((const uint4*)&g_mask[0][t][0][0])[tid];
            __syncthreads();

            float4 acc = {0, 0, 0, 0};
#pragma unroll
            for (int wd = 0; wd < 16; ++wd) {
                unsigned bits = stg[b * 16 + wd];
                const float* base = Wp + wd * 1024;
                while (bits) {
                    int k = __ffs(bits) - 1; bits &= bits - 1;
                    float4 w = *(const float4*)(base + k * 32);
                    acc.x += w.x; acc.y += w.y; acc.z += w.z; acc.w += w.w;
                }
            }
            float4 a = {x4.x + acc.x, x4.y + acc.y, x4.z + acc.z, x4.w + acc.w};
            float4 th, s;
            alif4(m, bb, sp, a, th, s);
            unsigned nb = (s.x != 0.f ? 1u : 0u) | (s.y != 0.f ? 2u : 0u) |
                          (s.z != 0.f ? 4u : 0u) | (s.w != 0.f ? 8u : 0u);
            nib[b * 8 + jg] = nb;
            sp = s;
            __syncthreads();
            if (tid < 64) {
                uint4 n0 = *(const uint4*)&nib[tid * 8];
                uint4 n1 = *(const uint4*)&nib[tid * 8 + 4];
                unsigned wo = n0.x | (n0.y << 4) | (n0.z << 8) | (n0.w << 12) |
                              (n1.x << 16) | (n1.y << 20) | (n1.z << 24) | (n1.w << 28);
                g_mask[0][t + 1][tid][jt] = wo;
            }
            __syncthreads();
            if (tid == 0) release_add(&g_r0[t + 1]);
        }
    } else {
        // ============ layers 1/2: 32 CTAs each, 32b x 32j, 2 matrices, split-K ============
        const int L = (cta < 48) ? 1 : 2;
        const int r = (cta - 16) & 31;
        const int jt = r & 15, half = r >> 4;
        const int j0 = jt * 32, b0 = half * 32;
        const int kh = tid >> 8, rem = tid & 255;
        const int bi = rem >> 3, jg = rem & 7;
        const int b = b0 + bi, j = j0 + jg * 4;

        const float* Win  = (L == 1) ? Wi2 : Wi3;
        const float* Wrec = (L == 1) ? Wh2 : Wh3;
        const float* bI   = (L == 1) ? bi2 : bi3;
        const float* bH   = (L == 1) ? bh2 : bh3;

        for (int idx = tid; idx < 512 * 32; idx += 512) {
            int jj = idx >> 9, h = idx & 511;
            Wa[h * 32 + jj] = Win[(size_t)(j0 + jj) * HID + h];
            Wb[h * 32 + jj] = Wrec[(size_t)(j0 + jj) * HID + h];
        }

        float4 bias = {bI[j] + bH[j], bI[j + 1] + bH[j + 1],
                       bI[j + 2] + bH[j + 2], bI[j + 3] + bH[j + 3]};
        float4 m = {0, 0, 0, 0}, sp = {0, 0, 0, 0};
        float4 bb = {0.01f, 0.01f, 0.01f, 0.01f};

        unsigned* stgA = stg;         // [32][16]
        unsigned* stgB = stg + 512;   // [32][16]
        const int wd0 = kh * 8;
        const float* WpA = Wa + jg * 4;
        const float* WpB = Wb + jg * 4;

        for (int t = 0; t < TSTEPS; ++t) {
            if (tid == 0) {
                if (L == 1) waitflag(&g_r0[t + 1], 16u);
                else        waitflag(&g_r1[half][t + 1], 16u);
            } else if (tid == 32) {
                if (L == 1) waitflag(&g_r1[half][t], 16u);
                else        waitflag(&g_r2[half][t], 16u);
            }
            __syncthreads();
            if (tid < 128) {
                ((uint4*)stgA)[tid] = (L == 1)
                    ? ((const uint4*)&g_mask[0][t + 1][b0][0])[tid]
                    : ((const uint4*)&g_mask[1][t + 1][b0][0])[tid];
            } else if (tid < 256) {
                ((uint4*)stgB)[tid - 128] = (L == 1)
                    ? ((const uint4*)&g_mask[1][t][b0][0])[tid - 128]
                    : ((const uint4*)&g_mask[2][t][b0][0])[tid - 128];
            }
            __syncthreads();

            float4 acc = {0, 0, 0, 0};
#pragma unroll
            for (int wq = 0; wq < 8; ++wq) {
                int wd = wd0 + wq;
                unsigned bits = stgA[bi * 16 + wd];
                const float* basep = WpA + wd * 1024;
                while (bits) {
                    int k = __ffs(bits) - 1; bits &= bits - 1;
                    float4 w = *(const float4*)(basep + k * 32);
                    acc.x += w.x; acc.y += w.y; acc.z += w.z; acc.w += w.w;
                }
                bits = stgB[bi * 16 + wd];
                basep = WpB + wd * 1024;
                while (bits) {
                    int k = __ffs(bits) - 1; bits &= bits - 1;
                    float4 w = *(const float4*)(basep + k * 32);
                    acc.x += w.x; acc.y += w.y; acc.z += w.z; acc.w += w.w;
                }
            }
            if (kh == 1) *(float4*)&red[rem * 4] = acc;
            __syncthreads();
            if (kh == 0) {
                float4 o = *(const float4*)&red[rem * 4];
                float4 a = {bias.x + acc.x + o.x, bias.y + acc.y + o.y,
                            bias.z + acc.z + o.z, bias.w + acc.w + o.w};
                float4 th, s;
                alif4(m, bb, sp, a, th, s);
                unsigned nb = (s.x != 0.f ? 1u : 0u) | (s.y != 0.f ? 2u : 0u) |
                              (s.z != 0.f ? 4u : 0u) | (s.w != 0.f ? 8u : 0u);
                nib[bi * 8 + jg] = nb;
                sp = s;
                if (L == 2) {
                    size_t basei = (size_t)(b * TSTEPS + t) * HID + j;
                    *(float4*)&out[SPK_OFF + basei] = s;
                    *(float4*)&out[MEM_OFF + basei] = m;
                    *(float4*)&out[TH_OFF + basei]  = th;
                }
            }
            __syncthreads();
            if (tid < 32) {
                uint4 n0 = *(const uint4*)&nib[tid * 8];
                uint4 n1 = *(const uint4*)&nib[tid * 8 + 4];
                unsigned wo = n0.x | (n0.y << 4) | (n0.z << 8) | (n0.w << 12) |
                              (n1.x << 16) | (n1.y << 20) | (n1.z << 24) | (n1.w << 28);
                g_mask[L][t + 1][b0 + tid][jt] = wo;
            }
            __syncthreads();
            if (tid == 0) {
                if (L == 1) release_add(&g_r1[half][t + 1]);
                else        release_add(&g_r2[half][t + 1]);
            }
        }
    }
}

// ---------------- output = mem3 @ Wo^T + bo ----------------
__global__ __launch_bounds__(256) void out_gemm(const float* __restrict__ Wo,
                                                const float* __restrict__ bo,
                                                float* __restrict__ out)
{
    const float* mem = out + MEM_OFF;
    int warp = threadIdx.x / 32, lane = threadIdx.x % 32;
    int row = blockIdx.x * 8 + warp;

    float mreg[16];
#pragma unroll
    for (int kk = 0; kk < 16; ++kk)
        mreg[kk] = mem[(size_t)row * HID + kk * 32 + lane];

#pragma unroll 4
    for (int o = 0; o < OUTDIM; ++o) {
        float s = 0.f;
#pragma unroll
        for (int kk = 0; kk < 16; ++kk)
            s += mreg[kk] * __ldg(&Wo[(size_t)o * HID + kk * 32 + lane]);
#pragma unroll
        for (int off = 16; off; off >>= 1)
            s += __shfl_xor_sync(0xffffffffu, s, off);
        if (lane == 0)
            out[OUT_OFF + (size_t)row * OUTDIM + o] = s + __ldg(&bo[o]);
    }
}

// ---------------- launch ----------------
extern "C" void kernel_launch(void* const* d_in, const int* in_sizes, int n_in,
                              void* d_out, int out_size)
{
    const float* x   = (const float*)d_in[0];
    const float* Wi1 = (const float*)d_in[1];
    const float* bi1 = (const float*)d_in[2];
    const float* Wh1 = (const float*)d_in[3];
    const float* bh1 = (const float*)d_in[4];
    const float* Wi2 = (const float*)d_in[5];
    const float* bi2 = (const float*)d_in[6];
    const float* Wh2 = (const float*)d_in[7];
    const float* bh2 = (const float*)d_in[8];
    const float* Wi3 = (const float*)d_in[9];
    const float* bi3 = (const float*)d_in[10];
    const float* Wh3 = (const float*)d_in[11];
    const float* bh3 = (const float*)d_in[12];
    const float* Wo  = (const float*)d_in[13];
    const float* bo  = (const float*)d_in[14];
    float* out = (float*)d_out;

    cudaFuncSetAttribute(alif_persistent,
                         cudaFuncAttributeMaxDynamicSharedMemorySize, SMEM_BYTES);

    init_kernel<<<16, 256>>>();
    alif_persistent<<<148, 512, SMEM_BYTES>>>(x, Wi1, bi1, bh1,
                                              Wh1, Wi2, bi2, Wh2, bh2,
                                              Wi3, bi3, Wh3, bh3, out);
    out_gemm<<<(BATCH * TSTEPS) / 8, 256>>>(Wo, bo, out);
}

// round 13
// speedup vs baseline: 3.3463x; 1.0354x over previous
#include <cuda_runtime.h>
#include <cstdint>

// ---------------- problem constants ----------------
#define BATCH 64
#define TSTEPS 500
#define INDIM 700
#define HID 512
#define OUTDIM 20

#define OUT_OFF 0
#define SPK_OFF 640000
#define MEM_OFF 17024000
#define TH_OFF  33408000

#define ALPHA_C   0.9512294245007140f
#define OMALPHA_C 0.0487705754992860f
#define RO_C      0.9983347214509673f
#define OMRO_C    0.0016652785490327f

// ---------------- static device scratch ----------------
// g_X1 layout: [t*64 + b][j]  (t-major: one GEMM y-tile = one t-pair, all batches)
__device__ float    g_X1[(size_t)BATCH * TSTEPS * HID];
__device__ unsigned g_mask[3][TSTEPS + 1][BATCH][16];    // spike bitmasks
__device__ unsigned g_r0[TSTEPS + 1];                    // layer0 group flags
__device__ unsigned g_r1[2][TSTEPS + 1];                 // layer1 per-half flags
__device__ unsigned g_r2[2][TSTEPS + 1];                 // layer2 per-half flags
__device__ unsigned g_xf[256];                           // X1 y-tile flags (target 4)

// ---------------- init: flags + t=0 masks ----------------
__global__ void init_kernel()
{
    int idx = blockIdx.x * blockDim.x + threadIdx.x;
    int n = gridDim.x * blockDim.x;
    for (int i = idx; i < TSTEPS + 1; i += n)
        g_r0[i] = (i == 0) ? 16u : 0u;
    for (int i = idx; i < 2 * (TSTEPS + 1); i += n)
        ((unsigned*)g_r1)[i] = ((i % (TSTEPS + 1)) == 0) ? 16u : 0u;
    for (int i = idx; i < 2 * (TSTEPS + 1); i += n)
        ((unsigned*)g_r2)[i] = ((i % (TSTEPS + 1)) == 0) ? 16u : 0u;
    for (int i = idx; i < 256; i += n)
        g_xf[i] = 0u;
    for (int i = idx; i < 3 * BATCH * 16; i += n) {
        int L = i / (BATCH * 16);
        int r = i % (BATCH * 16);
        g_mask[L][0][r / 16][r % 16] = 0u;
    }
}

// ---------------- sync helpers (frozen protocol) ----------------
__device__ __forceinline__ void waitflag(const unsigned* p, unsigned target)
{
    unsigned v;
    do {
        asm volatile("ld.acquire.gpu.u32 %0, [%1];" : "=r"(v) : "l"(p) : "memory");
    } while (v < target);
}

__device__ __forceinline__ void release_add(unsigned* p)
{
    asm volatile("red.release.gpu.add.u32 [%0], 1;" :: "l"(p) : "memory");
}

// ---------------- ALIF vector update (frozen arithmetic) ----------------
__device__ __forceinline__ void alif4(float4& m, float4& bb, float4& sp,
                                      const float4 a, float4& th, float4& s)
{
    bb.x = RO_C * bb.x + OMRO_C * sp.x;
    bb.y = RO_C * bb.y + OMRO_C * sp.y;
    bb.z = RO_C * bb.z + OMRO_C * sp.z;
    bb.w = RO_C * bb.w + OMRO_C * sp.w;
    th.x = 0.01f + 1.8f * bb.x;
    th.y = 0.01f + 1.8f * bb.y;
    th.z = 0.01f + 1.8f * bb.z;
    th.w = 0.01f + 1.8f * bb.w;
    m.x = m.x * ALPHA_C + OMALPHA_C * a.x - th.x * sp.x;
    m.y = m.y * ALPHA_C + OMALPHA_C * a.y - th.y * sp.y;
    m.z = m.z * ALPHA_C + OMALPHA_C * a.z - th.z * sp.z;
    m.w = m.w * ALPHA_C + OMALPHA_C * a.w - th.w * sp.w;
    s.x = (m.x - th.x > 0.f) ? 1.f : 0.f;
    s.y = (m.y - th.y > 0.f) ? 1.f : 0.f;
    s.z = (m.z - th.z > 0.f) ? 1.f : 0.f;
    s.w = (m.w - th.w > 0.f) ? 1.f : 0.f;
}

// smem layout (dynamic): Wa 64KB | Wb 64KB | stg 8KB | red 4KB | nib 2KB
// x1-group CTAs reuse the same region as As 8KB | Bs 8KB.
#define SMEM_BYTES (65536 + 65536 + 8192 + 4096 + 2048)

// ---------------- fused persistent kernel ----------------
// Grid = 148 CTAs x 512 thr, 1 CTA/SM.
//  [0,16)   L0 ALIF   [16,80) L1/L2 ALIF
//  [80,148) x1 GEMM workers, then fused out-GEMM consumers (behind g_r2)
__global__ __launch_bounds__(512, 1) void alif_persistent(
    const float* __restrict__ x,
    const float* __restrict__ Wi1, const float* __restrict__ bi1,
    const float* __restrict__ bh1,
    const float* __restrict__ Wh1,
    const float* __restrict__ Wi2, const float* __restrict__ bi2,
    const float* __restrict__ Wh2, const float* __restrict__ bh2,
    const float* __restrict__ Wi3, const float* __restrict__ bi3,
    const float* __restrict__ Wh3, const float* __restrict__ bh3,
    const float* __restrict__ Wo, const float* __restrict__ bo,
    float* __restrict__ out)
{
    extern __shared__ unsigned char smraw[];
    const int cta = blockIdx.x;
    const int tid = threadIdx.x;

    if (cta >= 80) {
        // ================= x1 GEMM group: 68 CTAs over 1000 tiles (verbatim r9) =================
        float (*As)[128] = (float (*)[128])smraw;            // [16][128]
        float (*Bs)[128] = (float (*)[128])(smraw + 8192);   // [16][128]

        const int tr = (tid / 16) * 4;
        const int tc = (tid % 16) * 8;

        for (int tile = cta - 80; tile < 1000; tile += 68) {
            const int yb = tile >> 2;
            const int mBase = yb * 128;
            const int nBase = (tile & 3) * 128;

            float acc[4][8];
#pragma unroll
            for (int i = 0; i < 4; ++i)
#pragma unroll
                for (int jj = 0; jj < 8; ++jj) acc[i][jj] = 0.f;

            for (int k0 = 0; k0 < INDIM; k0 += 16) {
                {
                    int row = tid >> 2;
                    int kq = (tid & 3) * 4;
                    int k = k0 + kq;
                    int R = mBase + row;
                    int tt = R >> 6, bb2 = R & 63;
                    float4 v = make_float4(0.f, 0.f, 0.f, 0.f);
                    const float* src = &x[((size_t)bb2 * TSTEPS + tt) * INDIM + k];
                    if (k + 3 < INDIM) {
                        v = *(const float4*)src;
                    } else {
                        float t0 = (k + 0 < INDIM) ? src[0] : 0.f;
                        float t1 = (k + 1 < INDIM) ? src[1] : 0.f;
                        float t2 = (k + 2 < INDIM) ? src[2] : 0.f;
                        float t3 = (k + 3 < INDIM) ? src[3] : 0.f;
                        v = make_float4(t0, t1, t2, t3);
                    }
                    As[kq + 0][row] = v.x; As[kq + 1][row] = v.y;
                    As[kq + 2][row] = v.z; As[kq + 3][row] = v.w;

                    float4 u = make_float4(0.f, 0.f, 0.f, 0.f);
                    const float* srcB = &Wi1[(size_t)(nBase + row) * INDIM + k];
                    if (k + 3 < INDIM) {
                        u = *(const float4*)srcB;
                    } else {
                        float t0 = (k + 0 < INDIM) ? srcB[0] : 0.f;
                        float t1 = (k + 1 < INDIM) ? srcB[1] : 0.f;
                        float t2 = (k + 2 < INDIM) ? srcB[2] : 0.f;
                        float t3 = (k + 3 < INDIM) ? srcB[3] : 0.f;
                        u = make_float4(t0, t1, t2, t3);
                    }
                    Bs[kq + 0][row] = u.x; Bs[kq + 1][row] = u.y;
                    Bs[kq + 2][row] = u.z; Bs[kq + 3][row] = u.w;
                }
                __syncthreads();

#pragma unroll
                for (int kk = 0; kk < 16; ++kk) {
                    float a[4], b[8];
                    *(float4*)&a[0] = *(float4*)&As[kk][tr];
                    *(float4*)&b[0] = *(float4*)&Bs[kk][tc];
                    *(float4*)&b[4] = *(float4*)&Bs[kk][tc + 4];
#pragma unroll
                    for (int i = 0; i < 4; ++i)
#pragma unroll
                        for (int jj = 0; jj < 8; ++jj) acc[i][jj] += a[i] * b[jj];
                }
                __syncthreads();
            }

            float bj[8];
#pragma unroll
            for (int jj = 0; jj < 8; ++jj) {
                int j = nBase + tc + jj;
                bj[jj] = bi1[j] + bh1[j];
            }
#pragma unroll
            for (int i = 0; i < 4; ++i) {
                size_t m = (size_t)(mBase + tr + i);
                float4 v0 = make_float4(acc[i][0] + bj[0], acc[i][1] + bj[1],
                                        acc[i][2] + bj[2], acc[i][3] + bj[3]);
                float4 v1 = make_float4(acc[i][4] + bj[4], acc[i][5] + bj[5],
                                        acc[i][6] + bj[6], acc[i][7] + bj[7]);
                *(float4*)&g_X1[m * HID + nBase + tc] = v0;
                *(float4*)&g_X1[m * HID + nBase + tc + 4] = v1;
            }
            __syncthreads();
            if (tid == 0) release_add(&g_xf[yb]);
        }

        // ================= fused out-GEMM: consume mem3 behind proven g_r2 flags ========
        // Proven consumer shape: tid0 acquire-poll -> __syncthreads -> weak reads.
        {
            const int w = tid >> 5, lane = tid & 31;
            const float* mem = out + MEM_OFF;
            for (int t = cta - 80; t < TSTEPS; t += 68) {
                if (tid == 0) {
                    waitflag(&g_r2[0][t + 1], 16u);
                    waitflag(&g_r2[1][t + 1], 16u);
                }
                __syncthreads();
#pragma unroll
                for (int bq = 0; bq < 4; ++bq) {
                    int b = w * 4 + bq;
                    size_t rowbase = (size_t)b * TSTEPS + t;
                    float mreg[16];
#pragma unroll
                    for (int kk = 0; kk < 16; ++kk)
                        mreg[kk] = mem[rowbase * HID + kk * 32 + lane];
#pragma unroll 4
                    for (int o = 0; o < OUTDIM; ++o) {
                        float s = 0.f;
#pragma unroll
                        for (int kk = 0; kk < 16; ++kk)
                            s += mreg[kk] * __ldg(&Wo[(size_t)o * HID + kk * 32 + lane]);
#pragma unroll
                        for (int off = 16; off; off >>= 1)
                            s += __shfl_xor_sync(0xffffffffu, s, off);
                        if (lane == 0)
                            out[OUT_OFF + rowbase * OUTDIM + o] = s + __ldg(&bo[o]);
                    }
                }
                __syncthreads();
            }
        }
        return;
    }

    float*    Wa  = (float*)smraw;                               // [512][32]
    float*    Wb  = (float*)(smraw + 65536);                     // [512][32]
    unsigned* stg = (unsigned*)(smraw + 131072);                 // [2][64][16] (L0: [64][16])
    float*    red = (float*)(smraw + 131072 + 8192);             // [256][4]
    unsigned* nib = (unsigned*)(smraw + 131072 + 8192 + 4096);   // [64][8]

    if (cta < 16) {
        // ================= layer 0: 16 CTAs, each 64b x 32j, 1 matrix =================
        const int jt = cta, j0 = jt * 32;
        const int b = tid >> 3, jg = tid & 7;
        const int j = j0 + jg * 4;

        for (int idx = tid; idx < 512 * 32; idx += 512) {
            int jj = idx >> 9, h = idx & 511;
            Wa[h * 32 + jj] = Wh1[(size_t)(j0 + jj) * HID + h];
        }

        float4 m = {0, 0, 0, 0}, sp = {0, 0, 0, 0};
        float4 bb = {0.01f, 0.01f, 0.01f, 0.01f};
        const float* Wp = Wa + jg * 4;

        for (int t = 0; t < TSTEPS; ++t) {
            if (tid == 0) {
                waitflag(&g_xf[t >> 1], 4u);   // X1 tile for this t-pair ready
                waitflag(&g_r0[t], 16u);
            }
            __syncthreads();
            float4 x4 = *(const float4*)&g_X1[((size_t)t * 64 + b) * HID + j];
            if (tid < 256)
                ((uint4*)stg)[tid] = ((const uint4*)&g_mask[0][t][0][0])[tid];
            __syncthreads();

            float4 acc = {0, 0, 0, 0};
#pragma unroll
            for (int wd = 0; wd < 16; ++wd) {
                unsigned bits = stg[b * 16 + wd];
                const float* base = Wp + wd * 1024;
                while (bits) {
                    int k = __ffs(bits) - 1; bits &= bits - 1;
                    float4 w = *(const float4*)(base + k * 32);
                    acc.x += w.x; acc.y += w.y; acc.z += w.z; acc.w += w.w;
                }
            }
            float4 a = {x4.x + acc.x, x4.y + acc.y, x4.z + acc.z, x4.w + acc.w};
            float4 th, s;
            alif4(m, bb, sp, a, th, s);
            unsigned nb = (s.x != 0.f ? 1u : 0u) | (s.y != 0.f ? 2u : 0u) |
                          (s.z != 0.f ? 4u : 0u) | (s.w != 0.f ? 8u : 0u);
            nib[b * 8 + jg] = nb;
            sp = s;
            __syncthreads();
            if (tid < 64) {
                uint4 n0 = *(const uint4*)&nib[tid * 8];
                uint4 n1 = *(const uint4*)&nib[tid * 8 + 4];
                unsigned wo = n0.x | (n0.y << 4) | (n0.z << 8) | (n0.w << 12) |
                              (n1.x << 16) | (n1.y << 20) | (n1.z << 24) | (n1.w << 28);
                g_mask[0][t + 1][tid][jt] = wo;
            }
            __syncthreads();
            if (tid == 0) release_add(&g_r0[t + 1]);
        }
    } else {
        // ============ layers 1/2: 32 CTAs each, 32b x 32j, 2 matrices, split-K ============
        const int L = (cta < 48) ? 1 : 2;
        const int r = (cta - 16) & 31;
        const int jt = r & 15, half = r >> 4;
        const int j0 = jt * 32, b0 = half * 32;
        const int kh = tid >> 8, rem = tid & 255;
        const int bi = rem >> 3, jg = rem & 7;
        const int b = b0 + bi, j = j0 + jg * 4;

        const float* Win  = (L == 1) ? Wi2 : Wi3;
        const float* Wrec = (L == 1) ? Wh2 : Wh3;
        const float* bI   = (L == 1) ? bi2 : bi3;
        const float* bH   = (L == 1) ? bh2 : bh3;

        for (int idx = tid; idx < 512 * 32; idx += 512) {
            int jj = idx >> 9, h = idx & 511;
            Wa[h * 32 + jj] = Win[(size_t)(j0 + jj) * HID + h];
            Wb[h * 32 + jj] = Wrec[(size_t)(j0 + jj) * HID + h];
        }

        float4 bias = {bI[j] + bH[j], bI[j + 1] + bH[j + 1],
                       bI[j + 2] + bH[j + 2], bI[j + 3] + bH[j + 3]};
        float4 m = {0, 0, 0, 0}, sp = {0, 0, 0, 0};
        float4 bb = {0.01f, 0.01f, 0.01f, 0.01f};

        unsigned* stgA = stg;         // [32][16]
        unsigned* stgB = stg + 512;   // [32][16]
        const int wd0 = kh * 8;
        const float* WpA = Wa + jg * 4;
        const float* WpB = Wb + jg * 4;

        for (int t = 0; t < TSTEPS; ++t) {
            if (tid == 0) {
                if (L == 1) waitflag(&g_r0[t + 1], 16u);
                else        waitflag(&g_r1[half][t + 1], 16u);
            } else if (tid == 32) {
                if (L == 1) waitflag(&g_r1[half][t], 16u);
                else        waitflag(&g_r2[half][t], 16u);
            }
            __syncthreads();
            if (tid < 128) {
                ((uint4*)stgA)[tid] = (L == 1)
                    ? ((const uint4*)&g_mask[0][t + 1][b0][0])[tid]
                    : ((const uint4*)&g_mask[1][t + 1][b0][0])[tid];
            } else if (tid < 256) {
                ((uint4*)stgB)[tid - 128] = (L == 1)
                    ? ((const uint4*)&g_mask[1][t][b0][0])[tid - 128]
                    : ((const uint4*)&g_mask[2][t][b0][0])[tid - 128];
            }
            __syncthreads();

            float4 acc = {0, 0, 0, 0};
#pragma unroll
            for (int wq = 0; wq < 8; ++wq) {
                int wd = wd0 + wq;
                unsigned bits = stgA[bi * 16 + wd];
                const float* basep = WpA + wd * 1024;
                while (bits) {
                    int k = __ffs(bits) - 1; bits &= bits - 1;
                    float4 w = *(const float4*)(basep + k * 32);
                    acc.x += w.x; acc.y += w.y; acc.z += w.z; acc.w += w.w;
                }
                bits = stgB[bi * 16 + wd];
                basep = WpB + wd * 1024;
                while (bits) {
                    int k = __ffs(bits) - 1; bits &= bits - 1;
                    float4 w = *(const float4*)(basep + k * 32);
                    acc.x += w.x; acc.y += w.y; acc.z += w.z; acc.w += w.w;
                }
            }
            if (kh == 1) *(float4*)&red[rem * 4] = acc;
            __syncthreads();
            if (kh == 0) {
                float4 o = *(const float4*)&red[rem * 4];
                float4 a = {bias.x + acc.x + o.x, bias.y + acc.y + o.y,
                            bias.z + acc.z + o.z, bias.w + acc.w + o.w};
                float4 th, s;
                alif4(m, bb, sp, a, th, s);
                unsigned nb = (s.x != 0.f ? 1u : 0u) | (s.y != 0.f ? 2u : 0u) |
                              (s.z != 0.f ? 4u : 0u) | (s.w != 0.f ? 8u : 0u);
                nib[bi * 8 + jg] = nb;
                sp = s;
                if (L == 2) {
                    size_t basei = (size_t)(b * TSTEPS + t) * HID + j;
                    *(float4*)&out[SPK_OFF + basei] = s;
                    *(float4*)&out[MEM_OFF + basei] = m;
                    *(float4*)&out[TH_OFF + basei]  = th;
                }
            }
            __syncthreads();
            if (tid < 32) {
                uint4 n0 = *(const uint4*)&nib[tid * 8];
                uint4 n1 = *(const uint4*)&nib[tid * 8 + 4];
                unsigned wo = n0.x | (n0.y << 4) | (n0.z << 8) | (n0.w << 12) |
                              (n1.x << 16) | (n1.y << 20) | (n1.z << 24) | (n1.w << 28);
                g_mask[L][t + 1][b0 + tid][jt] = wo;
            }
            __syncthreads();
            if (tid == 0) {
                if (L == 1) release_add(&g_r1[half][t + 1]);
                else        release_add(&g_r2[half][t + 1]);
            }
        }
    }
}

// ---------------- launch ----------------
extern "C" void kernel_launch(void* const* d_in, const int* in_sizes, int n_in,
                              void* d_out, int out_size)
{
    const float* x   = (const float*)d_in[0];
    const float* Wi1 = (const float*)d_in[1];
    const float* bi1 = (const float*)d_in[2];
    const float* Wh1 = (const float*)d_in[3];
    const float* bh1 = (const float*)d_in[4];
    const float* Wi2 = (const float*)d_in[5];
    const float* bi2 = (const float*)d_in[6];
    const float* Wh2 = (const float*)d_in[7];
    const float* bh2 = (const float*)d_in[8];
    const float* Wi3 = (const float*)d_in[9];
    const float* bi3 = (const float*)d_in[10];
    const float* Wh3 = (const float*)d_in[11];
    const float* bh3 = (const float*)d_in[12];
    const float* Wo  = (const float*)d_in[13];
    const float* bo  = (const float*)d_in[14];
    float* out = (float*)d_out;

    cudaFuncSetAttribute(alif_persistent,
                         cudaFuncAttributeMaxDynamicSharedMemorySize, SMEM_BYTES);

    init_kernel<<<16, 256>>>();
    alif_persistent<<<148, 512, SMEM_BYTES>>>(x, Wi1, bi1, bh1,
                                              Wh1, Wi2, bi2, Wh2, bh2,
                                              Wi3, bi3, Wh3, bh3,
                                              Wo, bo, out);
}

// round 14
// speedup vs baseline: 3.4362x; 1.0269x over previous
#include <cuda_runtime.h>
#include <cstdint>

// ---------------- problem constants ----------------
#define BATCH 64
#define TSTEPS 500
#define INDIM 700
#define HID 512
#define OUTDIM 20

#define OUT_OFF 0
#define SPK_OFF 640000
#define MEM_OFF 17024000
#define TH_OFF  33408000

#define ALPHA_C   0.9512294245007140f
#define OMALPHA_C 0.0487705754992860f
#define RO_C      0.9983347214509673f
#define OMRO_C    0.0016652785490327f

// ---------------- static device scratch ----------------
// g_X1 layout: [t*64 + b][j]  (t-major: one GEMM y-tile = one t-pair, all batches)
__device__ float    g_X1[(size_t)BATCH * TSTEPS * HID];
__device__ unsigned g_mask[3][TSTEPS + 1][BATCH][16];    // spike bitmasks
__device__ unsigned g_r0[TSTEPS + 1];                    // layer0 group flags
__device__ unsigned g_r1[2][TSTEPS + 1];                 // layer1 per-half flags
__device__ unsigned g_r2[2][TSTEPS + 1];                 // layer2 per-half flags
__device__ unsigned g_xf[256];                           // X1 y-tile flags (target 8)

// ---------------- init: flags + t=0 masks ----------------
__global__ void init_kernel()
{
    int idx = blockIdx.x * blockDim.x + threadIdx.x;
    int n = gridDim.x * blockDim.x;
    for (int i = idx; i < TSTEPS + 1; i += n)
        g_r0[i] = (i == 0) ? 16u : 0u;
    for (int i = idx; i < 2 * (TSTEPS + 1); i += n)
        ((unsigned*)g_r1)[i] = ((i % (TSTEPS + 1)) == 0) ? 16u : 0u;
    for (int i = idx; i < 2 * (TSTEPS + 1); i += n)
        ((unsigned*)g_r2)[i] = ((i % (TSTEPS + 1)) == 0) ? 16u : 0u;
    for (int i = idx; i < 256; i += n)
        g_xf[i] = 0u;
    for (int i = idx; i < 3 * BATCH * 16; i += n) {
        int L = i / (BATCH * 16);
        int r = i % (BATCH * 16);
        g_mask[L][0][r / 16][r % 16] = 0u;
    }
}

// ---------------- sync helpers (frozen protocol) ----------------
__device__ __forceinline__ void waitflag(const unsigned* p, unsigned target)
{
    unsigned v;
    do {
        asm volatile("ld.acquire.gpu.u32 %0, [%1];" : "=r"(v) : "l"(p) : "memory");
    } while (v < target);
}

__device__ __forceinline__ void release_add(unsigned* p)
{
    asm volatile("red.release.gpu.add.u32 [%0], 1;" :: "l"(p) : "memory");
}

// ---------------- ALIF vector update (frozen arithmetic) ----------------
__device__ __forceinline__ void alif4(float4& m, float4& bb, float4& sp,
                                      const float4 a, float4& th, float4& s)
{
    bb.x = RO_C * bb.x + OMRO_C * sp.x;
    bb.y = RO_C * bb.y + OMRO_C * sp.y;
    bb.z = RO_C * bb.z + OMRO_C * sp.z;
    bb.w = RO_C * bb.w + OMRO_C * sp.w;
    th.x = 0.01f + 1.8f * bb.x;
    th.y = 0.01f + 1.8f * bb.y;
    th.z = 0.01f + 1.8f * bb.z;
    th.w = 0.01f + 1.8f * bb.w;
    m.x = m.x * ALPHA_C + OMALPHA_C * a.x - th.x * sp.x;
    m.y = m.y * ALPHA_C + OMALPHA_C * a.y - th.y * sp.y;
    m.z = m.z * ALPHA_C + OMALPHA_C * a.z - th.z * sp.z;
    m.w = m.w * ALPHA_C + OMALPHA_C * a.w - th.w * sp.w;
    s.x = (m.x - th.x > 0.f) ? 1.f : 0.f;
    s.y = (m.y - th.y > 0.f) ? 1.f : 0.f;
    s.z = (m.z - th.z > 0.f) ? 1.f : 0.f;
    s.w = (m.w - th.w > 0.f) ? 1.f : 0.f;
}

// smem layout (dynamic): Wa 64KB | Wb 64KB | stg 8KB | red 4KB | nib 2KB
// x1-group CTAs reuse the same region as As 8KB | Bs 4KB.
#define SMEM_BYTES (65536 + 65536 + 8192 + 4096 + 2048)

// ---------------- fused persistent kernel ----------------
// Grid = 148 CTAs x 512 thr, 1 CTA/SM.
//  [0,16)   L0 ALIF   [16,80) L1/L2 ALIF
//  [80,148) x1 GEMM workers (128x64 tiles), then fused out-GEMM (behind g_r2)
__global__ __launch_bounds__(512, 1) void alif_persistent(
    const float* __restrict__ x,
    const float* __restrict__ Wi1, const float* __restrict__ bi1,
    const float* __restrict__ bh1,
    const float* __restrict__ Wh1,
    const float* __restrict__ Wi2, const float* __restrict__ bi2,
    const float* __restrict__ Wh2, const float* __restrict__ bh2,
    const float* __restrict__ Wi3, const float* __restrict__ bi3,
    const float* __restrict__ Wh3, const float* __restrict__ bh3,
    const float* __restrict__ Wo, const float* __restrict__ bo,
    float* __restrict__ out)
{
    extern __shared__ unsigned char smraw[];
    const int cta = blockIdx.x;
    const int tid = threadIdx.x;

    if (cta >= 80) {
        // ========= x1 GEMM group: 68 CTAs over 2000 tiles of 128 rows x 64 j =========
        float (*As)[128] = (float (*)[128])smraw;            // [16][128]
        float (*Bs)[64]  = (float (*)[64])(smraw + 8192);    // [16][64]

        const int tr = (tid / 16) * 4;    // 4 rows per thread
        const int tc = (tid % 16) * 4;    // 4 cols per thread

        for (int tile = cta - 80; tile < 2000; tile += 68) {
            const int yb = tile >> 3;          // t-pair index (8 tiles per yb)
            const int mBase = yb * 128;
            const int nBase = (tile & 7) * 64;

            float acc[4][4];
#pragma unroll
            for (int i = 0; i < 4; ++i)
#pragma unroll
                for (int jj = 0; jj < 4; ++jj) acc[i][jj] = 0.f;

            for (int k0 = 0; k0 < INDIM; k0 += 16) {
                {
                    int row = tid >> 2;
                    int kq = (tid & 3) * 4;
                    int k = k0 + kq;
                    int R = mBase + row;
                    int tt = R >> 6, bb2 = R & 63;
                    float4 v = make_float4(0.f, 0.f, 0.f, 0.f);
                    const float* src = &x[((size_t)bb2 * TSTEPS + tt) * INDIM + k];
                    if (k + 3 < INDIM) {
                        v = *(const float4*)src;
                    } else {
                        float t0 = (k + 0 < INDIM) ? src[0] : 0.f;
                        float t1 = (k + 1 < INDIM) ? src[1] : 0.f;
                        float t2 = (k + 2 < INDIM) ? src[2] : 0.f;
                        float t3 = (k + 3 < INDIM) ? src[3] : 0.f;
                        v = make_float4(t0, t1, t2, t3);
                    }
                    As[kq + 0][row] = v.x; As[kq + 1][row] = v.y;
                    As[kq + 2][row] = v.z; As[kq + 3][row] = v.w;
                }
                if (tid < 256) {
                    int row = tid >> 2;        // 0..63 (j rows of this tile)
                    int kq = (tid & 3) * 4;
                    int k = k0 + kq;
                    float4 u = make_float4(0.f, 0.f, 0.f, 0.f);
                    const float* srcB = &Wi1[(size_t)(nBase + row) * INDIM + k];
                    if (k + 3 < INDIM) {
                        u = *(const float4*)srcB;
                    } else {
                        float t0 = (k + 0 < INDIM) ? srcB[0] : 0.f;
                        float t1 = (k + 1 < INDIM) ? srcB[1] : 0.f;
                        float t2 = (k + 2 < INDIM) ? srcB[2] : 0.f;
                        float t3 = (k + 3 < INDIM) ? srcB[3] : 0.f;
                        u = make_float4(t0, t1, t2, t3);
                    }
                    Bs[kq + 0][row] = u.x; Bs[kq + 1][row] = u.y;
                    Bs[kq + 2][row] = u.z; Bs[kq + 3][row] = u.w;
                }
                __syncthreads();

#pragma unroll
                for (int kk = 0; kk < 16; ++kk) {
                    float a[4], b[4];
                    *(float4*)&a[0] = *(float4*)&As[kk][tr];
                    *(float4*)&b[0] = *(float4*)&Bs[kk][tc];
#pragma unroll
                    for (int i = 0; i < 4; ++i)
#pragma unroll
                        for (int jj = 0; jj < 4; ++jj) acc[i][jj] += a[i] * b[jj];
                }
                __syncthreads();
            }

            float bj[4];
#pragma unroll
            for (int jj = 0; jj < 4; ++jj) {
                int j = nBase + tc + jj;
                bj[jj] = bi1[j] + bh1[j];
            }
#pragma unroll
            for (int i = 0; i < 4; ++i) {
                size_t m = (size_t)(mBase + tr + i);
                float4 v0 = make_float4(acc[i][0] + bj[0], acc[i][1] + bj[1],
                                        acc[i][2] + bj[2], acc[i][3] + bj[3]);
                *(float4*)&g_X1[m * HID + nBase + tc] = v0;
            }
            __syncthreads();
            if (tid == 0) release_add(&g_xf[yb]);
        }

        // ================= fused out-GEMM: consume mem3 behind proven g_r2 flags ========
        {
            const int w = tid >> 5, lane = tid & 31;
            const float* mem = out + MEM_OFF;
            for (int t = cta - 80; t < TSTEPS; t += 68) {
                if (tid == 0) {
                    waitflag(&g_r2[0][t + 1], 16u);
                    waitflag(&g_r2[1][t + 1], 16u);
                }
                __syncthreads();
#pragma unroll
                for (int bq = 0; bq < 4; ++bq) {
                    int b = w * 4 + bq;
                    size_t rowbase = (size_t)b * TSTEPS + t;
                    float mreg[16];
#pragma unroll
                    for (int kk = 0; kk < 16; ++kk)
                        mreg[kk] = mem[rowbase * HID + kk * 32 + lane];
#pragma unroll 4
                    for (int o = 0; o < OUTDIM; ++o) {
                        float s = 0.f;
#pragma unroll
                        for (int kk = 0; kk < 16; ++kk)
                            s += mreg[kk] * __ldg(&Wo[(size_t)o * HID + kk * 32 + lane]);
#pragma unroll
                        for (int off = 16; off; off >>= 1)
                            s += __shfl_xor_sync(0xffffffffu, s, off);
                        if (lane == 0)
                            out[OUT_OFF + rowbase * OUTDIM + o] = s + __ldg(&bo[o]);
                    }
                }
                __syncthreads();
            }
        }
        return;
    }

    float*    Wa  = (float*)smraw;                               // [512][32]
    float*    Wb  = (float*)(smraw + 65536);                     // [512][32]
    unsigned* stg = (unsigned*)(smraw + 131072);                 // [2][64][16] (L0: [64][16])
    float*    red = (float*)(smraw + 131072 + 8192);             // [256][4]
    unsigned* nib = (unsigned*)(smraw + 131072 + 8192 + 4096);   // [64][8]

    if (cta < 16) {
        // ================= layer 0: 16 CTAs, each 64b x 32j, 1 matrix =================
        const int jt = cta, j0 = jt * 32;
        const int b = tid >> 3, jg = tid & 7;
        const int j = j0 + jg * 4;

        for (int idx = tid; idx < 512 * 32; idx += 512) {
            int jj = idx >> 9, h = idx & 511;
            Wa[h * 32 + jj] = Wh1[(size_t)(j0 + jj) * HID + h];
        }

        float4 m = {0, 0, 0, 0}, sp = {0, 0, 0, 0};
        float4 bb = {0.01f, 0.01f, 0.01f, 0.01f};
        const float* Wp = Wa + jg * 4;

        for (int t = 0; t < TSTEPS; ++t) {
            if (tid == 0) {
                waitflag(&g_xf[t >> 1], 8u);   // X1 t-pair ready (8 tiles now)
                waitflag(&g_r0[t], 16u);
            }
            __syncthreads();
            float4 x4 = *(const float4*)&g_X1[((size_t)t * 64 + b) * HID + j];
            if (tid < 256)
                ((uint4*)stg)[tid] = ((const uint4*)&g_mask[0][t][0][0])[tid];
            __syncthreads();

            float4 acc = {0, 0, 0, 0};
#pragma unroll
            for (int wd = 0; wd < 16; ++wd) {
                unsigned bits = stg[b * 16 + wd];
                const float* base = Wp + wd * 1024;
                while (bits) {
                    int k = __ffs(bits) - 1; bits &= bits - 1;
                    float4 w = *(const float4*)(base + k * 32);
                    acc.x += w.x; acc.y += w.y; acc.z += w.z; acc.w += w.w;
                }
            }
            float4 a = {x4.x + acc.x, x4.y + acc.y, x4.z + acc.z, x4.w + acc.w};
            float4 th, s;
            alif4(m, bb, sp, a, th, s);
            unsigned nb = (s.x != 0.f ? 1u : 0u) | (s.y != 0.f ? 2u : 0u) |
                          (s.z != 0.f ? 4u : 0u) | (s.w != 0.f ? 8u : 0u);
            nib[b * 8 + jg] = nb;
            sp = s;
            __syncthreads();
            if (tid < 64) {
                uint4 n0 = *(const uint4*)&nib[tid * 8];
                uint4 n1 = *(const uint4*)&nib[tid * 8 + 4];
                unsigned wo = n0.x | (n0.y << 4) | (n0.z << 8) | (n0.w << 12) |
                              (n1.x << 16) | (n1.y << 20) | (n1.z << 24) | (n1.w << 28);
                g_mask[0][t + 1][tid][jt] = wo;
            }
            __syncthreads();
            if (tid == 0) release_add(&g_r0[t + 1]);
        }
    } else {
        // ============ layers 1/2: 32 CTAs each, 32b x 32j, 2 matrices, split-K ============
        const int L = (cta < 48) ? 1 : 2;
        const int r = (cta - 16) & 31;
        const int jt = r & 15, half = r >> 4;
        const int j0 = jt * 32, b0 = half * 32;
        const int kh = tid >> 8, rem = tid & 255;
        const int bi = rem >> 3, jg = rem & 7;
        const int b = b0 + bi, j = j0 + jg * 4;

        const float* Win  = (L == 1) ? Wi2 : Wi3;
        const float* Wrec = (L == 1) ? Wh2 : Wh3;
        const float* bI   = (L == 1) ? bi2 : bi3;
        const float* bH   = (L == 1) ? bh2 : bh3;

        for (int idx = tid; idx < 512 * 32; idx += 512) {
            int jj = idx >> 9, h = idx & 511;
            Wa[h * 32 + jj] = Win[(size_t)(j0 + jj) * HID + h];
            Wb[h * 32 + jj] = Wrec[(size_t)(j0 + jj) * HID + h];
        }

        float4 bias = {bI[j] + bH[j], bI[j + 1] + bH[j + 1],
                       bI[j + 2] + bH[j + 2], bI[j + 3] + bH[j + 3]};
        float4 m = {0, 0, 0, 0}, sp = {0, 0, 0, 0};
        float4 bb = {0.01f, 0.01f, 0.01f, 0.01f};

        unsigned* stgA = stg;         // [32][16]
        unsigned* stgB = stg + 512;   // [32][16]
        const int wd0 = kh * 8;
        const float* WpA = Wa + jg * 4;
        const float* WpB = Wb + jg * 4;

        for (int t = 0; t < TSTEPS; ++t) {
            if (tid == 0) {
                if (L == 1) waitflag(&g_r0[t + 1], 16u);
                else        waitflag(&g_r1[half][t + 1], 16u);
            } else if (tid == 32) {
                if (L == 1) waitflag(&g_r1[half][t], 16u);
                else        waitflag(&g_r2[half][t], 16u);
            }
            __syncthreads();
            if (tid < 128) {
                ((uint4*)stgA)[tid] = (L == 1)
                    ? ((const uint4*)&g_mask[0][t + 1][b0][0])[tid]
                    : ((const uint4*)&g_mask[1][t + 1][b0][0])[tid];
            } else if (tid < 256) {
                ((uint4*)stgB)[tid - 128] = (L == 1)
                    ? ((const uint4*)&g_mask[1][t][b0][0])[tid - 128]
                    : ((const uint4*)&g_mask[2][t][b0][0])[tid - 128];
            }
            __syncthreads();

            float4 acc = {0, 0, 0, 0};
#pragma unroll
            for (int wq = 0; wq < 8; ++wq) {
                int wd = wd0 + wq;
                unsigned bits = stgA[bi * 16 + wd];
                const float* basep = WpA + wd * 1024;
                while (bits) {
                    int k = __ffs(bits) - 1; bits &= bits - 1;
                    float4 w = *(const float4*)(basep + k * 32);
                    acc.x += w.x; acc.y += w.y; acc.z += w.z; acc.w += w.w;
                }
                bits = stgB[bi * 16 + wd];
                basep = WpB + wd * 1024;
                while (bits) {
                    int k = __ffs(bits) - 1; bits &= bits - 1;
                    float4 w = *(const float4*)(basep + k * 32);
                    acc.x += w.x; acc.y += w.y; acc.z += w.z; acc.w += w.w;
                }
            }
            if (kh == 1) *(float4*)&red[rem * 4] = acc;
            __syncthreads();
            if (kh == 0) {
                float4 o = *(const float4*)&red[rem * 4];
                float4 a = {bias.x + acc.x + o.x, bias.y + acc.y + o.y,
                            bias.z + acc.z + o.z, bias.w + acc.w + o.w};
                float4 th, s;
                alif4(m, bb, sp, a, th, s);
                unsigned nb = (s.x != 0.f ? 1u : 0u) | (s.y != 0.f ? 2u : 0u) |
                              (s.z != 0.f ? 4u : 0u) | (s.w != 0.f ? 8u : 0u);
                nib[bi * 8 + jg] = nb;
                sp = s;
                if (L == 2) {
                    size_t basei = (size_t)(b * TSTEPS + t) * HID + j;
                    *(float4*)&out[SPK_OFF + basei] = s;
                    *(float4*)&out[MEM_OFF + basei] = m;
                    *(float4*)&out[TH_OFF + basei]  = th;
                }
            }
            __syncthreads();
            if (tid < 32) {
                uint4 n0 = *(const uint4*)&nib[tid * 8];
                uint4 n1 = *(const uint4*)&nib[tid * 8 + 4];
                unsigned wo = n0.x | (n0.y << 4) | (n0.z << 8) | (n0.w << 12) |
                              (n1.x << 16) | (n1.y << 20) | (n1.z << 24) | (n1.w << 28);
                g_mask[L][t + 1][b0 + tid][jt] = wo;
            }
            __syncthreads();
            if (tid == 0) {
                if (L == 1) release_add(&g_r1[half][t + 1]);
                else        release_add(&g_r2[half][t + 1]);
            }
        }
    }
}

// ---------------- launch ----------------
extern "C" void kernel_launch(void* const* d_in, const int* in_sizes, int n_in,
                              void* d_out, int out_size)
{
    const float* x   = (const float*)d_in[0];
    const float* Wi1 = (const float*)d_in[1];
    const float* bi1 = (const float*)d_in[2];
    const float* Wh1 = (const float*)d_in[3];
    const float* bh1 = (const float*)d_in[4];
    const float* Wi2 = (const float*)d_in[5];
    const float* bi2 = (const float*)d_in[6];
    const float* Wh2 = (const float*)d_in[7];
    const float* bh2 = (const float*)d_in[8];
    const float* Wi3 = (const float*)d_in[9];
    const float* bi3 = (const float*)d_in[10];
    const float* Wh3 = (const float*)d_in[11];
    const float* bh3 = (const float*)d_in[12];
    const float* Wo  = (const float*)d_in[13];
    const float* bo  = (const float*)d_in[14];
    float* out = (float*)d_out;

    cudaFuncSetAttribute(alif_persistent,
                         cudaFuncAttributeMaxDynamicSharedMemorySize, SMEM_BYTES);

    init_kernel<<<16, 256>>>();
    alif_persistent<<<148, 512, SMEM_BYTES>>>(x, Wi1, bi1, bh1,
                                              Wh1, Wi2, bi2, Wh2, bh2,
                                              Wi3, bi3, Wh3, bh3,
                                              Wo, bo, out);
}